// round 8
// baseline (speedup 1.0000x reference)
#include <cuda_runtime.h>
#include <cstdint>

// Problem constants
#define BATCH   32
#define CIN     256
#define NPIX    4096          // 64*64
#define HEADS   4
#define DH      32
#define HID     128           // HEADS*DH
#define O3      384           // 3*HID
#define EPS     1e-5f

// ---------------------------------------------------------------------------
// Scratch (device globals: allocation-free)
// ---------------------------------------------------------------------------
__device__ float g_qkv [(size_t)BATCH * O3  * NPIX];   // 201 MB
__device__ float g_attn[(size_t)BATCH * HID * NPIX];   //  67 MB
__device__ float g_stats[BATCH * 2];                   // sum, sumsq per batch
__device__ float g_kmax [BATCH * HEADS * 32];
__device__ float g_kinv [BATCH * HEADS * 32];
__device__ float g_ctx  [BATCH * HEADS * 32 * 32];     // 512 KB

// ---------------------------------------------------------------------------
// K0: zero the accumulators (stats + ctx)
// ---------------------------------------------------------------------------
#define ZERO_N (BATCH * HEADS * 32 * 32 + BATCH * 2)
__global__ void k_zero() {
    const int i = blockIdx.x * blockDim.x + threadIdx.x;
    if (i < BATCH * HEADS * 32 * 32) g_ctx[i] = 0.f;
    else if (i < ZERO_N) g_stats[i - BATCH * HEADS * 32 * 32] = 0.f;
}

// ---------------------------------------------------------------------------
// helpers (all sm_80-baseline PTX: compiles at compute_103)
// ---------------------------------------------------------------------------
__device__ __forceinline__ float to_tf32(float x) {
    uint32_t u;
    asm("cvt.rna.tf32.f32 %0, %1;" : "=r"(u) : "f"(x));
    return __uint_as_float(u);
}
__device__ __forceinline__ void mma_tf32(float c[4],
                                         const uint32_t a[4],
                                         const uint32_t b[2]) {
    asm volatile(
        "mma.sync.aligned.m16n8k8.row.col.f32.tf32.tf32.f32 "
        "{%0,%1,%2,%3}, {%4,%5,%6,%7}, {%8,%9}, {%0,%1,%2,%3};"
        : "+f"(c[0]), "+f"(c[1]), "+f"(c[2]), "+f"(c[3])
        : "r"(a[0]), "r"(a[1]), "r"(a[2]), "r"(a[3]),
          "r"(b[0]), "r"(b[1]));
}
__device__ __forceinline__ void cpasync16(uint32_t s, const void* g) {
    asm volatile("cp.async.cg.shared.global [%0], [%1], 16;"
                 :: "r"(s), "l"(g) : "memory");
}
#define CP_COMMIT() asm volatile("cp.async.commit_group;" ::: "memory")
#define CP_WAIT2()  asm volatile("cp.async.wait_group 2;"  ::: "memory")

// smem column swizzle (period-16 in k): conflict-free for staging + fragments.
__device__ __forceinline__ int swz(int k) {
    return (((k & 3) ^ ((k >> 2) & 3)) << 3);   // {0,8,16,24}
}

// ---------------------------------------------------------------------------
// tf32 tensor-core GEMM:  C[z][M][4096] = A[M,K] * B[z][K,4096]  (+bias,+stats)
// CTA tile 128x128, BK=32, 8 warps (2m x 4n), warp tile 64x32.
// B: cp.async 4-stage ring (distance 3). A: 2-stage smem, LDG dist-2 regs.
// Register fragment double-buffering inside each BK step.
// ---------------------------------------------------------------------------
#define MMA_SMEM ((2 + 4) * 32 * 128 * 4)   // A 2 stages + B 4 stages = 96 KB

template<int K, int M, bool EPI>
__global__ __launch_bounds__(256)
void k_mma(const float* __restrict__ A, const float* __restrict__ Bg,
           float* __restrict__ Cg, const float* __restrict__ bias)
{
    extern __shared__ float sm[];
    float (*As)[32][128] = (float (*)[32][128])sm;                 // 2 stages
    float (*Bs)[32][128] = (float (*)[32][128])(sm + 2 * 32 * 128);// 4 stages

    const int tid  = threadIdx.x, lane = tid & 31, wid = tid >> 5;
    const int wm   = wid >> 2, wn = wid & 3;
    const int tq   = lane & 3, gp = lane >> 2;
    const int bx   = blockIdx.x, mt = blockIdx.y, z = blockIdx.z;

    const float* Ap = A  + (size_t)mt * 128 * K;
    const float* Bp = Bg + (size_t)z * K * NPIX + bx * 128;

    // A loader: row am, k-col base ac (4 float4 = 16 k)
    const int am = tid & 127, ac = (tid >> 7) * 16;
    // B loader: row bkr (0..31), col base bcf (16 floats = 4 cp.async)
    const int bkr = tid >> 3;
    const int bcf = (tid & 7) * 16;
    const uint32_t bs_row =
        (uint32_t)__cvta_generic_to_shared(&Bs[0][0][0]) + (uint32_t)(bkr * 128 * 4);

    float acc[4][4][4];
    #pragma unroll
    for (int i = 0; i < 4; i++)
        #pragma unroll
        for (int j = 0; j < 4; j++)
            #pragma unroll
            for (int r = 0; r < 4; r++) acc[i][j][r] = 0.f;

    float4 ra[4];
    auto ldgA = [&](int t) {
        #pragma unroll
        for (int j = 0; j < 4; j++)
            ra[j] = *(const float4*)(Ap + (size_t)am * K + t * 32 + ac + j * 4);
    };
    auto stsA = [&](int t) {
        const int buf = t & 1;
        #pragma unroll
        for (int j = 0; j < 4; j++) {
            const float e[4] = { ra[j].x, ra[j].y, ra[j].z, ra[j].w };
            #pragma unroll
            for (int i = 0; i < 4; i++) {
                const int k = ac + j * 4 + i;
                As[buf][k][am ^ swz(k)] = to_tf32(e[i]);
            }
        }
    };
    auto cpB = [&](int t) {
        const float* src = Bp + (size_t)(t * 32 + bkr) * NPIX + bcf;
        const uint32_t dst0 = bs_row + (uint32_t)((t & 3) * 32 * 128 * 4);
        #pragma unroll
        for (int j = 0; j < 4; j++) {
            const int col = bcf + j * 4;
            cpasync16(dst0 + (uint32_t)((col ^ swz(bkr)) * 4), src + j * 4);
        }
    };

    uint32_t af[2][4][4], bf[2][4][2];
    auto ldf = [&](int abuf, int bbuf, int ks, int rb) {
        const int k0 = ks * 8 + tq, k1 = k0 + 4;
        const int g0 = swz(k0),     g1 = swz(k1);
        #pragma unroll
        for (int mf = 0; mf < 4; mf++) {
            const int m0 = wm * 64 + mf * 16 + gp;
            af[rb][mf][0] = __float_as_uint(As[abuf][k0][(m0    ) ^ g0]);
            af[rb][mf][1] = __float_as_uint(As[abuf][k0][(m0 + 8) ^ g0]);
            af[rb][mf][2] = __float_as_uint(As[abuf][k1][(m0    ) ^ g1]);
            af[rb][mf][3] = __float_as_uint(As[abuf][k1][(m0 + 8) ^ g1]);
        }
        #pragma unroll
        for (int nf = 0; nf < 4; nf++) {
            const int n0 = wn * 32 + nf * 8 + gp;
            bf[rb][nf][0] = __float_as_uint(to_tf32(Bs[bbuf][k0][n0 ^ g0]));
            bf[rb][nf][1] = __float_as_uint(to_tf32(Bs[bbuf][k1][n0 ^ g1]));
        }
    };

    constexpr int T = K / 32;   // QKV: 8, out-proj: 4

    // prologue: B stages 0..2 in flight; A stage 0 stored, stage 1 in regs
    ldgA(0);
    cpB(0); CP_COMMIT();
    cpB(1); CP_COMMIT();
    cpB(2); CP_COMMIT();
    stsA(0);
    ldgA(1);

    #pragma unroll 1
    for (int t = 0; t < T; t++) {
        CP_WAIT2();          // B stage t complete (commits = 3 + t)
        __syncthreads();     // As[t&1], Bs[t&3] visible to all warps
        const int abuf = t & 1, bbuf = t & 3;

        ldf(abuf, bbuf, 0, 0);
        #pragma unroll
        for (int ks = 0; ks < 4; ks++) {
            if (ks < 3) ldf(abuf, bbuf, ks + 1, (ks + 1) & 1);
            const int rb = ks & 1;
            #pragma unroll
            for (int mf = 0; mf < 4; mf++)
                #pragma unroll
                for (int nf = 0; nf < 4; nf++)
                    mma_tf32(acc[mf][nf], af[rb][mf], bf[rb][nf]);
        }

        if (t + 1 < T) stsA(t + 1);   // consume ra -> As[(t+1)&1] (safe: barrier)
        if (t + 2 < T) ldgA(t + 2);   // refill ra
        if (t + 3 < T) cpB(t + 3);
        CP_COMMIT();                  // empty commits in tail keep counts valid
    }

    // --- epilogue ---
    const int mg0 = mt * 128 + wm * 64;
    const int ng0 = bx * 128 + wn * 32;
    float* Cz = Cg + (size_t)z * M * NPIX;
    float lsum = 0.f, lsq = 0.f;

    #pragma unroll
    for (int mf = 0; mf < 4; mf++) {
        const int r0 = mg0 + mf * 16 + gp;
        const float bv0 = EPI ? bias[r0]     : 0.f;
        const float bv1 = EPI ? bias[r0 + 8] : 0.f;
        #pragma unroll
        for (int nf = 0; nf < 4; nf++) {
            const int c0 = ng0 + nf * 8 + tq * 2;
            float2 v0, v1;
            v0.x = acc[mf][nf][0] + bv0;
            v0.y = acc[mf][nf][1] + bv0;
            v1.x = acc[mf][nf][2] + bv1;
            v1.y = acc[mf][nf][3] + bv1;
            if (EPI) {
                lsum += v0.x + v0.y + v1.x + v1.y;
                lsq  += v0.x * v0.x + v0.y * v0.y + v1.x * v1.x + v1.y * v1.y;
            }
            *(float2*)&Cz[(size_t)r0       * NPIX + c0] = v0;
            *(float2*)&Cz[(size_t)(r0 + 8) * NPIX + c0] = v1;
        }
    }

    if (EPI) {
        __shared__ float rs[8], rq[8];
        #pragma unroll
        for (int o = 16; o; o >>= 1) {
            lsum += __shfl_xor_sync(0xffffffffu, lsum, o);
            lsq  += __shfl_xor_sync(0xffffffffu, lsq,  o);
        }
        if (lane == 0) { rs[wid] = lsum; rq[wid] = lsq; }
        __syncthreads();
        if (tid == 0) {
            float s = 0.f, q = 0.f;
            #pragma unroll
            for (int w = 0; w < 8; w++) { s += rs[w]; q += rq[w]; }
            atomicAdd(&g_stats[2 * z + 0], s);
            atomicAdd(&g_stats[2 * z + 1], q);
        }
    }
}

// ---------------------------------------------------------------------------
// K2a: k-softmax stats. One block per (h,b), warp wid owns row d=wid.
// ---------------------------------------------------------------------------
__global__ __launch_bounds__(1024)
void k_kstats()
{
    const int h = blockIdx.x, b = blockIdx.y;
    const int lane = threadIdx.x & 31, wid = threadIdx.x >> 5;
    const float4* kr = (const float4*)
        (g_qkv + ((size_t)b * O3 + HID + h * DH + wid) * NPIX);

    float m = -1e30f;
    #pragma unroll 4
    for (int n = lane; n < NPIX / 4; n += 32) {
        float4 v = kr[n];
        m = fmaxf(m, fmaxf(fmaxf(v.x, v.y), fmaxf(v.z, v.w)));
    }
    #pragma unroll
    for (int off = 16; off; off >>= 1)
        m = fmaxf(m, __shfl_xor_sync(0xffffffffu, m, off));
    float s = 0.f;
    #pragma unroll 4
    for (int n = lane; n < NPIX / 4; n += 32) {
        float4 v = kr[n];
        s += __expf(v.x - m) + __expf(v.y - m) + __expf(v.z - m) + __expf(v.w - m);
    }
    #pragma unroll
    for (int off = 16; off; off >>= 1)
        s += __shfl_xor_sync(0xffffffffu, s, off);
    if (lane == 0) {
        g_kmax[(b * HEADS + h) * 32 + wid] = m;
        g_kinv[(b * HEADS + h) * 32 + wid] = 1.f / s;
    }
}

// ---------------------------------------------------------------------------
// K2b: context partials, register-tiled 8x8. Block (chunk, h, b) = 512 cols.
// ---------------------------------------------------------------------------
#define CTX_SMEM (8192 * 4)   // 32 KB

__global__ __launch_bounds__(256)
void k_ctx()
{
    extern __shared__ float sm[];
    float* ks = sm;                 // [32][65]
    float* vs = sm + 32 * 65;       // [32][65]
    __shared__ float rowmax[32], rowinv[32];

    const int ch = blockIdx.x, h = blockIdx.y, b = blockIdx.z;
    const int tid = threadIdx.x;
    const int g = tid >> 4, t16 = tid & 15;
    const int d0 = (t16 >> 2) * 8, e0 = (t16 & 3) * 8;
    const int bh = b * HEADS + h;

    if (tid < 32) {
        rowmax[tid] = g_kmax[bh * 32 + tid];
        rowinv[tid] = g_kinv[bh * 32 + tid];
    }

    const float* kbase = g_qkv + ((size_t)b * O3 + HID     + h * DH) * NPIX;
    const float* vbase = g_qkv + ((size_t)b * O3 + 2 * HID + h * DH) * NPIX;

    const int r = tid >> 3, c0 = (tid & 7) * 8;   // staging map

    float acc[8][8];
    #pragma unroll
    for (int i = 0; i < 8; i++)
        #pragma unroll
        for (int j = 0; j < 8; j++) acc[i][j] = 0.f;

    __syncthreads();

    #pragma unroll 1
    for (int tile = 0; tile < 8; ++tile) {
        const int nc = ch * 512 + tile * 64;
        const float4 k0 = *(const float4*)(kbase + (size_t)r * NPIX + nc + c0);
        const float4 k1 = *(const float4*)(kbase + (size_t)r * NPIX + nc + c0 + 4);
        const float4 v0 = *(const float4*)(vbase + (size_t)r * NPIX + nc + c0);
        const float4 v1 = *(const float4*)(vbase + (size_t)r * NPIX + nc + c0 + 4);
        const float m = rowmax[r], iv = rowinv[r];
        float* kd = ks + r * 65 + c0;
        float* vd = vs + r * 65 + c0;
        kd[0] = __expf(k0.x - m) * iv; kd[1] = __expf(k0.y - m) * iv;
        kd[2] = __expf(k0.z - m) * iv; kd[3] = __expf(k0.w - m) * iv;
        kd[4] = __expf(k1.x - m) * iv; kd[5] = __expf(k1.y - m) * iv;
        kd[6] = __expf(k1.z - m) * iv; kd[7] = __expf(k1.w - m) * iv;
        vd[0] = v0.x; vd[1] = v0.y; vd[2] = v0.z; vd[3] = v0.w;
        vd[4] = v1.x; vd[5] = v1.y; vd[6] = v1.z; vd[7] = v1.w;
        __syncthreads();

        #pragma unroll
        for (int s = 0; s < 4; ++s) {
            const int j = g + s * 16;
            float ka[8], va[8];
            #pragma unroll
            for (int i = 0; i < 8; ++i) ka[i] = ks[(d0 + i) * 65 + j];
            #pragma unroll
            for (int i = 0; i < 8; ++i) va[i] = vs[(e0 + i) * 65 + j];
            #pragma unroll
            for (int i = 0; i < 8; ++i)
                #pragma unroll
                for (int jj = 0; jj < 8; ++jj)
                    acc[i][jj] += ka[i] * va[jj];
        }
        __syncthreads();
    }

    // tree reduction over the 16 groups (red aliases staging region)
    float* red = sm;
    #pragma unroll
    for (int step = 8; step >= 1; step >>= 1) {
        if (g >= step && g < 2 * step) {
            float* dst = red + ((g - step) * 16 + t16) * 64;
            #pragma unroll
            for (int q = 0; q < 64; ++q) dst[q] = acc[q >> 3][q & 7];
        }
        __syncthreads();
        if (g < step) {
            const float* src = red + (g * 16 + t16) * 64;
            #pragma unroll
            for (int q = 0; q < 64; ++q) acc[q >> 3][q & 7] += src[q];
        }
        __syncthreads();
    }
    if (g == 0) {
        float* dst = g_ctx + bh * 1024;
        #pragma unroll
        for (int i = 0; i < 8; ++i)
            #pragma unroll
            for (int jj = 0; jj < 8; ++jj)
                atomicAdd(&dst[(d0 + i) * 32 + (e0 + jj)], acc[i][jj]);
    }
}

// ---------------------------------------------------------------------------
// K2c: q softmax + out = ctx^T q.  Block (chunk, h, b) covers 1024 n-cols.
// ---------------------------------------------------------------------------
__global__ __launch_bounds__(256)
void k_qout()
{
    const int ch = blockIdx.x, h = blockIdx.y, b = blockIdx.z;
    const int tid = threadIdx.x;

    __shared__ float ctx[32][32];
    #pragma unroll
    for (int i = tid; i < 1024; i += 256)
        ctx[i >> 5][i & 31] = g_ctx[(b * HEADS + h) * 1024 + i];
    __syncthreads();

    const float* qbase = g_qkv  + ((size_t)b * O3  + h * DH) * NPIX;
    float*       obase = g_attn + ((size_t)b * HID + h * DH) * NPIX;
    const float scale = 0.17677669529663687f;   // 32^-0.5

    #pragma unroll 1
    for (int i = 0; i < 4; i++) {
        const int n = ch * 1024 + i * 256 + tid;
        float q[32];
        float m = -1e30f;
        #pragma unroll
        for (int dd = 0; dd < 32; dd++) {
            q[dd] = qbase[(size_t)dd * NPIX + n];
            m = fmaxf(m, q[dd]);
        }
        float s = 0.f;
        #pragma unroll
        for (int dd = 0; dd < 32; dd++) { q[dd] = __expf(q[dd] - m); s += q[dd]; }
        const float inv = scale / s;
        #pragma unroll
        for (int dd = 0; dd < 32; dd++) q[dd] *= inv;

        #pragma unroll
        for (int ee = 0; ee < 32; ee++) {
            float o = 0.f;
            #pragma unroll
            for (int dd = 0; dd < 32; dd++) o += ctx[dd][ee] * q[dd];
            obase[(size_t)ee * NPIX + n] = o;
        }
    }
}

// ---------------------------------------------------------------------------
// K4: in-place GroupNorm (per-batch stats) + per-channel affine
// ---------------------------------------------------------------------------
__global__ __launch_bounds__(256)
void k_gn(float* __restrict__ out,
          const float* __restrict__ gn_w,
          const float* __restrict__ gn_b)
{
    const size_t gid  = (size_t)blockIdx.x * blockDim.x + threadIdx.x;
    const size_t base = gid * 4;
    const int b = (int)(base >> 20);
    const int c = (int)((base >> 12) & 255);

    const float invN = 1.f / (256.f * 4096.f);
    const float mean = g_stats[2 * b + 0] * invN;
    const float var  = g_stats[2 * b + 1] * invN - mean * mean;
    const float r    = rsqrtf(var + EPS);
    const float w    = gn_w[c] * r;
    const float bb   = gn_b[c] - mean * w;

    float4 v = *(float4*)&out[base];
    v.x = v.x * w + bb;
    v.y = v.y * w + bb;
    v.z = v.z * w + bb;
    v.w = v.w * w + bb;
    *(float4*)&out[base] = v;
}

// ---------------------------------------------------------------------------
// Launch
// ---------------------------------------------------------------------------
extern "C" void kernel_launch(void* const* d_in, const int* in_sizes, int n_in,
                              void* d_out, int out_size)
{
    const float* x     = (const float*)d_in[0];
    const float* w_qkv = (const float*)d_in[1];
    const float* w_out = (const float*)d_in[2];
    const float* b_out = (const float*)d_in[3];
    const float* gn_w  = (const float*)d_in[4];
    const float* gn_b  = (const float*)d_in[5];
    float* out = (float*)d_out;

    float *p_qkv, *p_attn;
    cudaGetSymbolAddress((void**)&p_qkv,  g_qkv);
    cudaGetSymbolAddress((void**)&p_attn, g_attn);

    cudaFuncSetAttribute(k_mma<CIN, O3, false>,
                         cudaFuncAttributeMaxDynamicSharedMemorySize, MMA_SMEM);
    cudaFuncSetAttribute(k_mma<HID, CIN, true>,
                         cudaFuncAttributeMaxDynamicSharedMemorySize, MMA_SMEM);
    cudaFuncSetAttribute(k_ctx,
                         cudaFuncAttributeMaxDynamicSharedMemorySize, CTX_SMEM);

    // K0: zero stats + ctx
    k_zero<<<(ZERO_N + 255) / 256, 256>>>();

    // K1: QKV projection  [384,256] x [256,4096] per batch (tf32 HMMA)
    k_mma<CIN, O3, false>
        <<<dim3(NPIX / 128, O3 / 128, BATCH), 256, MMA_SMEM>>>(w_qkv, x, p_qkv, nullptr);

    // K2: attention core
    k_kstats<<<dim3(HEADS, BATCH), 1024>>>();
    k_ctx   <<<dim3(8, HEADS, BATCH), 256, CTX_SMEM>>>();
    k_qout  <<<dim3(4, HEADS, BATCH), 256>>>();

    // K3: output projection + bias + stats  [256,128] x [128,4096] per batch
    k_mma<HID, CIN, true>
        <<<dim3(NPIX / 128, CIN / 128, BATCH), 256, MMA_SMEM>>>(w_out, p_attn, out, b_out);

    // K4: GroupNorm normalize in place
    k_gn<<<(BATCH * CIN * NPIX / 4) / 256, 256>>>(out, gn_w, gn_b);
}

// round 9
// speedup vs baseline: 1.0311x; 1.0311x over previous
#include <cuda_runtime.h>
#include <cstdint>

// Problem constants
#define BATCH   32
#define CIN     256
#define NPIX    4096          // 64*64
#define HEADS   4
#define DH      32
#define HID     128           // HEADS*DH
#define O3      384           // 3*HID
#define EPS     1e-5f

// ---------------------------------------------------------------------------
// Scratch (device globals: allocation-free)
// ---------------------------------------------------------------------------
__device__ float g_qkv [(size_t)BATCH * O3  * NPIX];   // 201 MB
__device__ float g_attn[(size_t)BATCH * HID * NPIX];   //  67 MB
__device__ float g_stats[BATCH * 2];                   // sum, sumsq per batch
__device__ float g_ksum [BATCH * HEADS * 32];          // per-row exp sums
__device__ float g_ctx  [BATCH * HEADS * 32 * 32];     // unnormalized ctx

// ---------------------------------------------------------------------------
// K0: zero the accumulators (ctx + ksum + stats)
// ---------------------------------------------------------------------------
#define N_CTX  (BATCH * HEADS * 32 * 32)
#define N_KSUM (BATCH * HEADS * 32)
#define ZERO_N (N_CTX + N_KSUM + BATCH * 2)
__global__ void k_zero() {
    const int i = blockIdx.x * blockDim.x + threadIdx.x;
    if (i < N_CTX) g_ctx[i] = 0.f;
    else if (i < N_CTX + N_KSUM) g_ksum[i - N_CTX] = 0.f;
    else if (i < ZERO_N) g_stats[i - N_CTX - N_KSUM] = 0.f;
}

// ---------------------------------------------------------------------------
// helpers (all sm_80-baseline PTX: compiles at compute_103)
// ---------------------------------------------------------------------------
__device__ __forceinline__ float to_tf32(float x) {
    uint32_t u;
    asm("cvt.rna.tf32.f32 %0, %1;" : "=r"(u) : "f"(x));
    return __uint_as_float(u);
}
__device__ __forceinline__ void mma_tf32(float c[4],
                                         const uint32_t a[4],
                                         const uint32_t b[2]) {
    asm volatile(
        "mma.sync.aligned.m16n8k8.row.col.f32.tf32.tf32.f32 "
        "{%0,%1,%2,%3}, {%4,%5,%6,%7}, {%8,%9}, {%0,%1,%2,%3};"
        : "+f"(c[0]), "+f"(c[1]), "+f"(c[2]), "+f"(c[3])
        : "r"(a[0]), "r"(a[1]), "r"(a[2]), "r"(a[3]),
          "r"(b[0]), "r"(b[1]));
}
__device__ __forceinline__ void cpasync16(uint32_t s, const void* g) {
    asm volatile("cp.async.cg.shared.global [%0], [%1], 16;"
                 :: "r"(s), "l"(g) : "memory");
}
#define CP_COMMIT() asm volatile("cp.async.commit_group;" ::: "memory")
#define CP_WAIT2()  asm volatile("cp.async.wait_group 2;"  ::: "memory")

// smem column swizzle: conflict-free for staging and fragment access.
__device__ __forceinline__ int swz(int k) {
    return (((k & 3) ^ ((k >> 2) & 3)) << 3);   // {0,8,16,24}
}

// ---------------------------------------------------------------------------
// tf32 tensor-core GEMM (R7-best variant):
//   C[z][M][4096] = A[M,K] * B[z][K,4096]  (+bias, +stats)
// CTA tile 128x128, BK=16, 8 warps (2m x 4n), warp tile 64x32.
// Grid: (m-tiles, n-tiles, batch) -- m fastest so CTAs sharing the same
// activation B-tile are launch-adjacent (L2 reuse of x / attn).
// ---------------------------------------------------------------------------
#define MMA_SMEM ((2 + 4) * 16 * 128 * 4)   // A 2 stages + B 4 stages = 48 KB

template<int K, int M, bool EPI>
__global__ __launch_bounds__(256)
void k_mma(const float* __restrict__ A, const float* __restrict__ Bg,
           float* __restrict__ Cg, const float* __restrict__ bias)
{
    extern __shared__ float sm[];
    float (*As)[16][128] = (float (*)[16][128])sm;                 // 2 stages
    float (*Bs)[16][128] = (float (*)[16][128])(sm + 2 * 16 * 128);// 4 stages

    const int tid  = threadIdx.x, lane = tid & 31, wid = tid >> 5;
    const int wm   = wid >> 2, wn = wid & 3;
    const int tq   = lane & 3, gp = lane >> 2;
    const int mt   = blockIdx.x, nt = blockIdx.y, z = blockIdx.z;

    const float* Ap = A  + (size_t)mt * 128 * K;
    const float* Bp = Bg + (size_t)z * K * NPIX + nt * 128;

    // A loader: row am, col base ak (2 float4)
    const int am = tid & 127, ak = (tid >> 7) * 8;
    // B loader: row bkr (0..15), col bc (2 cp.async of 16B)
    const int bkr = tid >> 4;
    const int bc  = (tid & 15) * 8;
    const uint32_t bsw = (uint32_t)(bc ^ swz(bkr));
    const uint32_t bs_base =
        (uint32_t)__cvta_generic_to_shared(&Bs[0][0][0]) + (bkr * 128 + bsw) * 4;

    float acc[4][4][4];
    #pragma unroll
    for (int i = 0; i < 4; i++)
        #pragma unroll
        for (int j = 0; j < 4; j++)
            #pragma unroll
            for (int r = 0; r < 4; r++) acc[i][j][r] = 0.f;

    float4 ra[2];
    auto ldgA = [&](int t) {
        #pragma unroll
        for (int j = 0; j < 2; j++)
            ra[j] = *(const float4*)(Ap + (size_t)am * K + t * 16 + ak + j * 4);
    };
    auto stsA = [&](int t) {
        const int buf = t & 1;
        #pragma unroll
        for (int j = 0; j < 2; j++) {
            const float e[4] = { ra[j].x, ra[j].y, ra[j].z, ra[j].w };
            #pragma unroll
            for (int i = 0; i < 4; i++) {
                const int k = ak + j * 4 + i;
                As[buf][k][am ^ swz(k)] = to_tf32(e[i]);
            }
        }
    };
    auto cpB = [&](int t) {
        const float* src = Bp + (size_t)(t * 16 + bkr) * NPIX + bc;
        const uint32_t dst = bs_base + (uint32_t)((t & 3) * 16 * 128 * 4);
        cpasync16(dst,      src);
        cpasync16(dst + 16, src + 4);
    };
    auto compute = [&](int t) {
        const int abuf = t & 1, bbuf = t & 3;
        #pragma unroll
        for (int ks = 0; ks < 2; ks++) {
            const int k0 = ks * 8 + tq, k1 = k0 + 4;
            const int g0 = swz(k0),     g1 = swz(k1);
            uint32_t af[4][4], bf[4][2];
            #pragma unroll
            for (int mf = 0; mf < 4; mf++) {
                const int m0 = wm * 64 + mf * 16 + gp;
                af[mf][0] = __float_as_uint(As[abuf][k0][(m0    ) ^ g0]);
                af[mf][1] = __float_as_uint(As[abuf][k0][(m0 + 8) ^ g0]);
                af[mf][2] = __float_as_uint(As[abuf][k1][(m0    ) ^ g1]);
                af[mf][3] = __float_as_uint(As[abuf][k1][(m0 + 8) ^ g1]);
            }
            #pragma unroll
            for (int nf = 0; nf < 4; nf++) {
                const int n0 = wn * 32 + nf * 8 + gp;
                bf[nf][0] = __float_as_uint(to_tf32(Bs[bbuf][k0][n0 ^ g0]));
                bf[nf][1] = __float_as_uint(to_tf32(Bs[bbuf][k1][n0 ^ g1]));
            }
            #pragma unroll
            for (int mf = 0; mf < 4; mf++)
                #pragma unroll
                for (int nf = 0; nf < 4; nf++)
                    mma_tf32(acc[mf][nf], af[mf], bf[nf]);
        }
    };

    constexpr int T = K / 16;   // >= 8

    // prologue: B stages 0..2 in flight; A stage 0 stored, stage 1 in regs
    ldgA(0);
    cpB(0); CP_COMMIT();
    cpB(1); CP_COMMIT();
    cpB(2); CP_COMMIT();
    stsA(0);
    ldgA(1);

    #pragma unroll 4
    for (int t = 0; t < T; t++) {
        CP_WAIT2();          // B stage t complete (commits = 3 + t)
        __syncthreads();     // As[t&1] from prev iter + Bs[t&3] visible
        compute(t);
        if (t + 1 < T) stsA(t + 1);   // consume ra -> As[(t+1)&1]
        if (t + 2 < T) ldgA(t + 2);   // refill ra (L2-hot weights)
        if (t + 3 < T) cpB(t + 3);
        CP_COMMIT();         // empty commits in tail keep wait counting valid
    }

    // --- epilogue ---
    const int mg0 = mt * 128 + wm * 64;
    const int ng0 = nt * 128 + wn * 32;
    float* Cz = Cg + (size_t)z * M * NPIX;
    float lsum = 0.f, lsq = 0.f;

    #pragma unroll
    for (int mf = 0; mf < 4; mf++) {
        const int r0 = mg0 + mf * 16 + gp;
        const float bv0 = EPI ? bias[r0]     : 0.f;
        const float bv1 = EPI ? bias[r0 + 8] : 0.f;
        #pragma unroll
        for (int nf = 0; nf < 4; nf++) {
            const int c0 = ng0 + nf * 8 + tq * 2;
            float2 v0, v1;
            v0.x = acc[mf][nf][0] + bv0;
            v0.y = acc[mf][nf][1] + bv0;
            v1.x = acc[mf][nf][2] + bv1;
            v1.y = acc[mf][nf][3] + bv1;
            if (EPI) {
                lsum += v0.x + v0.y + v1.x + v1.y;
                lsq  += v0.x * v0.x + v0.y * v0.y + v1.x * v1.x + v1.y * v1.y;
            }
            *(float2*)&Cz[(size_t)r0       * NPIX + c0] = v0;
            *(float2*)&Cz[(size_t)(r0 + 8) * NPIX + c0] = v1;
        }
    }

    if (EPI) {
        __shared__ float rs[8], rq[8];
        #pragma unroll
        for (int o = 16; o; o >>= 1) {
            lsum += __shfl_xor_sync(0xffffffffu, lsum, o);
            lsq  += __shfl_xor_sync(0xffffffffu, lsq,  o);
        }
        if (lane == 0) { rs[wid] = lsum; rq[wid] = lsq; }
        __syncthreads();
        if (tid == 0) {
            float s = 0.f, q = 0.f;
            #pragma unroll
            for (int w = 0; w < 8; w++) { s += rs[w]; q += rq[w]; }
            atomicAdd(&g_stats[2 * z + 0], s);
            atomicAdd(&g_stats[2 * z + 1], q);
        }
    }
}

// ---------------------------------------------------------------------------
// K2b: context partials, register-tiled 8x8 + fused exp-sum accumulation.
// Block (chunk, h, b) covers 512 cols. Softmax needs no max subtraction here:
// k = x.w_qkv has |k| <~ 3 (std ~0.32), exp(k) is safely in fp32 range.
// ctxU (unnormalized) and per-row sums go to gmem; k_qout normalizes.
// ---------------------------------------------------------------------------
#define CTX_SMEM (8192 * 4)   // 32 KB

__global__ __launch_bounds__(256)
void k_ctx()
{
    extern __shared__ float sm[];
    float* ks = sm;                 // [32][65]
    float* vs = sm + 32 * 65;       // [32][65]

    const int ch = blockIdx.x, h = blockIdx.y, b = blockIdx.z;
    const int tid = threadIdx.x;
    const int g = tid >> 4, t16 = tid & 15;
    const int d0 = (t16 >> 2) * 8, e0 = (t16 & 3) * 8;
    const int bh = b * HEADS + h;

    const float* kbase = g_qkv + ((size_t)b * O3 + HID     + h * DH) * NPIX;
    const float* vbase = g_qkv + ((size_t)b * O3 + 2 * HID + h * DH) * NPIX;

    const int r = tid >> 3, c0 = (tid & 7) * 8;   // staging map

    float acc[8][8];
    #pragma unroll
    for (int i = 0; i < 8; i++)
        #pragma unroll
        for (int j = 0; j < 8; j++) acc[i][j] = 0.f;
    float esum = 0.f;

    #pragma unroll 1
    for (int tile = 0; tile < 8; ++tile) {
        const int nc = ch * 512 + tile * 64;
        const float4 k0 = *(const float4*)(kbase + (size_t)r * NPIX + nc + c0);
        const float4 k1 = *(const float4*)(kbase + (size_t)r * NPIX + nc + c0 + 4);
        const float4 v0 = *(const float4*)(vbase + (size_t)r * NPIX + nc + c0);
        const float4 v1 = *(const float4*)(vbase + (size_t)r * NPIX + nc + c0 + 4);
        float* kd = ks + r * 65 + c0;
        float* vd = vs + r * 65 + c0;
        float e0v = __expf(k0.x), e1v = __expf(k0.y);
        float e2v = __expf(k0.z), e3v = __expf(k0.w);
        float e4v = __expf(k1.x), e5v = __expf(k1.y);
        float e6v = __expf(k1.z), e7v = __expf(k1.w);
        kd[0] = e0v; kd[1] = e1v; kd[2] = e2v; kd[3] = e3v;
        kd[4] = e4v; kd[5] = e5v; kd[6] = e6v; kd[7] = e7v;
        esum += (e0v + e1v) + (e2v + e3v) + (e4v + e5v) + (e6v + e7v);
        vd[0] = v0.x; vd[1] = v0.y; vd[2] = v0.z; vd[3] = v0.w;
        vd[4] = v1.x; vd[5] = v1.y; vd[6] = v1.z; vd[7] = v1.w;
        __syncthreads();

        #pragma unroll
        for (int s = 0; s < 4; ++s) {
            const int j = g + s * 16;
            float ka[8], va[8];
            #pragma unroll
            for (int i = 0; i < 8; ++i) ka[i] = ks[(d0 + i) * 65 + j];
            #pragma unroll
            for (int i = 0; i < 8; ++i) va[i] = vs[(e0 + i) * 65 + j];
            #pragma unroll
            for (int i = 0; i < 8; ++i)
                #pragma unroll
                for (int jj = 0; jj < 8; ++jj)
                    acc[i][jj] += ka[i] * va[jj];
        }
        __syncthreads();
    }

    // per-row exp-sum: reduce across the 8 staging threads of row r
    #pragma unroll
    for (int o = 4; o; o >>= 1)
        esum += __shfl_xor_sync(0xffffffffu, esum, o);
    if ((tid & 7) == 0) atomicAdd(&g_ksum[bh * 32 + r], esum);

    // tree reduction over the 16 groups (red aliases staging region)
    float* red = sm;
    #pragma unroll
    for (int step = 8; step >= 1; step >>= 1) {
        if (g >= step && g < 2 * step) {
            float* dst = red + ((g - step) * 16 + t16) * 64;
            #pragma unroll
            for (int q = 0; q < 64; ++q) dst[q] = acc[q >> 3][q & 7];
        }
        __syncthreads();
        if (g < step) {
            const float* src = red + (g * 16 + t16) * 64;
            #pragma unroll
            for (int q = 0; q < 64; ++q) acc[q >> 3][q & 7] += src[q];
        }
        __syncthreads();
    }
    if (g == 0) {
        float* dst = g_ctx + bh * 1024;
        #pragma unroll
        for (int i = 0; i < 8; ++i)
            #pragma unroll
            for (int jj = 0; jj < 8; ++jj)
                atomicAdd(&dst[(d0 + i) * 32 + (e0 + jj)], acc[i][jj]);
    }
}

// ---------------------------------------------------------------------------
// K2c: q softmax (no max pass; |q| small) + out = ctx^T q, ctx normalized by
// the k exp-sums on load. Block (chunk, h, b) covers 1024 n-cols.
// ---------------------------------------------------------------------------
__global__ __launch_bounds__(256)
void k_qout()
{
    const int ch = blockIdx.x, h = blockIdx.y, b = blockIdx.z;
    const int tid = threadIdx.x;
    const int bh = b * HEADS + h;

    __shared__ float inv[32];
    __shared__ float ctx[32][32];
    if (tid < 32) inv[tid] = 1.f / g_ksum[bh * 32 + tid];
    __syncthreads();
    #pragma unroll
    for (int i = tid; i < 1024; i += 256)
        ctx[i >> 5][i & 31] = g_ctx[bh * 1024 + i] * inv[i >> 5];
    __syncthreads();

    const float* qbase = g_qkv  + ((size_t)b * O3  + h * DH) * NPIX;
    float*       obase = g_attn + ((size_t)b * HID + h * DH) * NPIX;
    const float scale = 0.17677669529663687f;   // 32^-0.5

    #pragma unroll 1
    for (int i = 0; i < 4; i++) {
        const int n = ch * 1024 + i * 256 + tid;
        float q[32];
        float s = 0.f;
        #pragma unroll
        for (int dd = 0; dd < 32; dd++) {
            q[dd] = __expf(qbase[(size_t)dd * NPIX + n]);
            s += q[dd];
        }
        const float iv = scale / s;
        #pragma unroll
        for (int dd = 0; dd < 32; dd++) q[dd] *= iv;

        #pragma unroll
        for (int ee = 0; ee < 32; ee++) {
            float o = 0.f;
            #pragma unroll
            for (int dd = 0; dd < 32; dd++) o += ctx[dd][ee] * q[dd];
            obase[(size_t)ee * NPIX + n] = o;
        }
    }
}

// ---------------------------------------------------------------------------
// K4: in-place GroupNorm (per-batch stats) + per-channel affine
// ---------------------------------------------------------------------------
__global__ __launch_bounds__(256)
void k_gn(float* __restrict__ out,
          const float* __restrict__ gn_w,
          const float* __restrict__ gn_b)
{
    const size_t gid  = (size_t)blockIdx.x * blockDim.x + threadIdx.x;
    const size_t base = gid * 4;
    const int b = (int)(base >> 20);
    const int c = (int)((base >> 12) & 255);

    const float invN = 1.f / (256.f * 4096.f);
    const float mean = g_stats[2 * b + 0] * invN;
    const float var  = g_stats[2 * b + 1] * invN - mean * mean;
    const float r    = rsqrtf(var + EPS);
    const float w    = gn_w[c] * r;
    const float bb   = gn_b[c] - mean * w;

    float4 v = *(float4*)&out[base];
    v.x = v.x * w + bb;
    v.y = v.y * w + bb;
    v.z = v.z * w + bb;
    v.w = v.w * w + bb;
    *(float4*)&out[base] = v;
}

// ---------------------------------------------------------------------------
// Launch
// ---------------------------------------------------------------------------
extern "C" void kernel_launch(void* const* d_in, const int* in_sizes, int n_in,
                              void* d_out, int out_size)
{
    const float* x     = (const float*)d_in[0];
    const float* w_qkv = (const float*)d_in[1];
    const float* w_out = (const float*)d_in[2];
    const float* b_out = (const float*)d_in[3];
    const float* gn_w  = (const float*)d_in[4];
    const float* gn_b  = (const float*)d_in[5];
    float* out = (float*)d_out;

    float *p_qkv, *p_attn;
    cudaGetSymbolAddress((void**)&p_qkv,  g_qkv);
    cudaGetSymbolAddress((void**)&p_attn, g_attn);

    cudaFuncSetAttribute(k_mma<CIN, O3, false>,
                         cudaFuncAttributeMaxDynamicSharedMemorySize, MMA_SMEM);
    cudaFuncSetAttribute(k_mma<HID, CIN, true>,
                         cudaFuncAttributeMaxDynamicSharedMemorySize, MMA_SMEM);
    cudaFuncSetAttribute(k_ctx,
                         cudaFuncAttributeMaxDynamicSharedMemorySize, CTX_SMEM);

    // K0: zero ctx + ksum + stats
    k_zero<<<(ZERO_N + 255) / 256, 256>>>();

    // K1: QKV projection  [384,256] x [256,4096] per batch (tf32 HMMA)
    // grid: m-tiles fastest so the 3 CTAs sharing a B tile are adjacent.
    k_mma<CIN, O3, false>
        <<<dim3(O3 / 128, NPIX / 128, BATCH), 256, MMA_SMEM>>>(w_qkv, x, p_qkv, nullptr);

    // K2: attention core (kstats fused into k_ctx)
    k_ctx <<<dim3(8, HEADS, BATCH), 256, CTX_SMEM>>>();
    k_qout<<<dim3(4, HEADS, BATCH), 256>>>();

    // K3: output projection + bias + stats  [256,128] x [128,4096] per batch
    k_mma<HID, CIN, true>
        <<<dim3(CIN / 128, NPIX / 128, BATCH), 256, MMA_SMEM>>>(w_out, p_attn, out, b_out);

    // K4: GroupNorm normalize in place
    k_gn<<<(BATCH * CIN * NPIX / 4) / 256, 256>>>(out, gn_w, gn_b);
}

// round 10
// speedup vs baseline: 1.8039x; 1.7495x over previous
#include <cuda_runtime.h>
#include <cstdint>

// Problem constants
#define BATCH   32
#define CIN     256
#define NPIX    4096          // 64*64
#define HEADS   4
#define DH      32
#define HID     128           // HEADS*DH
#define O3      384           // 3*HID
#define EPS     1e-5f

// ---------------------------------------------------------------------------
// Scratch (device globals: allocation-free)
// ---------------------------------------------------------------------------
__device__ float g_qkv [(size_t)BATCH * O3  * NPIX];   // 201 MB
__device__ float g_attn[(size_t)BATCH * HID * NPIX];   //  67 MB
__device__ float g_stats[BATCH * 2];                   // sum, sumsq per batch
__device__ float g_ksum [BATCH * HEADS * 32];          // per-row exp sums
__device__ float g_ctx  [BATCH * HEADS * 32 * 32];     // unnormalized ctx

// ---------------------------------------------------------------------------
// K0: zero the accumulators (ctx + ksum + stats)
// ---------------------------------------------------------------------------
#define N_CTX  (BATCH * HEADS * 32 * 32)
#define N_KSUM (BATCH * HEADS * 32)
#define ZERO_N (N_CTX + N_KSUM + BATCH * 2)
__global__ void k_zero() {
    const int i = blockIdx.x * blockDim.x + threadIdx.x;
    if (i < N_CTX) g_ctx[i] = 0.f;
    else if (i < N_CTX + N_KSUM) g_ksum[i - N_CTX] = 0.f;
    else if (i < ZERO_N) g_stats[i - N_CTX - N_KSUM] = 0.f;
}

// ---------------------------------------------------------------------------
// helpers (all sm_80-baseline PTX: compiles at compute_103)
// ---------------------------------------------------------------------------
__device__ __forceinline__ float to_tf32(float x) {
    uint32_t u;
    asm("cvt.rna.tf32.f32 %0, %1;" : "=r"(u) : "f"(x));
    return __uint_as_float(u);
}
__device__ __forceinline__ void mma_tf32(float c[4],
                                         const uint32_t a[4],
                                         const uint32_t b[2]) {
    asm volatile(
        "mma.sync.aligned.m16n8k8.row.col.f32.tf32.tf32.f32 "
        "{%0,%1,%2,%3}, {%4,%5,%6,%7}, {%8,%9}, {%0,%1,%2,%3};"
        : "+f"(c[0]), "+f"(c[1]), "+f"(c[2]), "+f"(c[3])
        : "r"(a[0]), "r"(a[1]), "r"(a[2]), "r"(a[3]),
          "r"(b[0]), "r"(b[1]));
}
__device__ __forceinline__ void cpasync16(uint32_t s, const void* g) {
    asm volatile("cp.async.cg.shared.global [%0], [%1], 16;"
                 :: "r"(s), "l"(g) : "memory");
}
#define CP_COMMIT() asm volatile("cp.async.commit_group;" ::: "memory")
#define CP_WAIT2()  asm volatile("cp.async.wait_group 2;"  ::: "memory")

// smem column swizzle: conflict-free for staging and fragment access.
__device__ __forceinline__ int swz(int k) {
    return (((k & 3) ^ ((k >> 2) & 3)) << 3);   // {0,8,16,24}
}

// ---------------------------------------------------------------------------
// tf32 tensor-core GEMM (R7-best variant):
//   C[z][M][4096] = A[M,K] * B[z][K,4096]  (+bias, +stats)
// CTA tile 128x128, BK=16, 8 warps (2m x 4n), warp tile 64x32.
// ---------------------------------------------------------------------------
#define MMA_SMEM ((2 + 4) * 16 * 128 * 4)   // A 2 stages + B 4 stages = 48 KB

template<int K, int M, bool EPI>
__global__ __launch_bounds__(256)
void k_mma(const float* __restrict__ A, const float* __restrict__ Bg,
           float* __restrict__ Cg, const float* __restrict__ bias)
{
    extern __shared__ float sm[];
    float (*As)[16][128] = (float (*)[16][128])sm;                 // 2 stages
    float (*Bs)[16][128] = (float (*)[16][128])(sm + 2 * 16 * 128);// 4 stages

    const int tid  = threadIdx.x, lane = tid & 31, wid = tid >> 5;
    const int wm   = wid >> 2, wn = wid & 3;
    const int tq   = lane & 3, gp = lane >> 2;
    const int mt   = blockIdx.x, nt = blockIdx.y, z = blockIdx.z;

    const float* Ap = A  + (size_t)mt * 128 * K;
    const float* Bp = Bg + (size_t)z * K * NPIX + nt * 128;

    const int am = tid & 127, ak = (tid >> 7) * 8;
    const int bkr = tid >> 4;
    const int bc  = (tid & 15) * 8;
    const uint32_t bsw = (uint32_t)(bc ^ swz(bkr));
    const uint32_t bs_base =
        (uint32_t)__cvta_generic_to_shared(&Bs[0][0][0]) + (bkr * 128 + bsw) * 4;

    float acc[4][4][4];
    #pragma unroll
    for (int i = 0; i < 4; i++)
        #pragma unroll
        for (int j = 0; j < 4; j++)
            #pragma unroll
            for (int r = 0; r < 4; r++) acc[i][j][r] = 0.f;

    float4 ra[2];
    auto ldgA = [&](int t) {
        #pragma unroll
        for (int j = 0; j < 2; j++)
            ra[j] = *(const float4*)(Ap + (size_t)am * K + t * 16 + ak + j * 4);
    };
    auto stsA = [&](int t) {
        const int buf = t & 1;
        #pragma unroll
        for (int j = 0; j < 2; j++) {
            const float e[4] = { ra[j].x, ra[j].y, ra[j].z, ra[j].w };
            #pragma unroll
            for (int i = 0; i < 4; i++) {
                const int k = ak + j * 4 + i;
                As[buf][k][am ^ swz(k)] = to_tf32(e[i]);
            }
        }
    };
    auto cpB = [&](int t) {
        const float* src = Bp + (size_t)(t * 16 + bkr) * NPIX + bc;
        const uint32_t dst = bs_base + (uint32_t)((t & 3) * 16 * 128 * 4);
        cpasync16(dst,      src);
        cpasync16(dst + 16, src + 4);
    };
    auto compute = [&](int t) {
        const int abuf = t & 1, bbuf = t & 3;
        #pragma unroll
        for (int ks = 0; ks < 2; ks++) {
            const int k0 = ks * 8 + tq, k1 = k0 + 4;
            const int g0 = swz(k0),     g1 = swz(k1);
            uint32_t af[4][4], bf[4][2];
            #pragma unroll
            for (int mf = 0; mf < 4; mf++) {
                const int m0 = wm * 64 + mf * 16 + gp;
                af[mf][0] = __float_as_uint(As[abuf][k0][(m0    ) ^ g0]);
                af[mf][1] = __float_as_uint(As[abuf][k0][(m0 + 8) ^ g0]);
                af[mf][2] = __float_as_uint(As[abuf][k1][(m0    ) ^ g1]);
                af[mf][3] = __float_as_uint(As[abuf][k1][(m0 + 8) ^ g1]);
            }
            #pragma unroll
            for (int nf = 0; nf < 4; nf++) {
                const int n0 = wn * 32 + nf * 8 + gp;
                bf[nf][0] = __float_as_uint(to_tf32(Bs[bbuf][k0][n0 ^ g0]));
                bf[nf][1] = __float_as_uint(to_tf32(Bs[bbuf][k1][n0 ^ g1]));
            }
            #pragma unroll
            for (int mf = 0; mf < 4; mf++)
                #pragma unroll
                for (int nf = 0; nf < 4; nf++)
                    mma_tf32(acc[mf][nf], af[mf], bf[nf]);
        }
    };

    constexpr int T = K / 16;   // >= 8

    ldgA(0);
    cpB(0); CP_COMMIT();
    cpB(1); CP_COMMIT();
    cpB(2); CP_COMMIT();
    stsA(0);
    ldgA(1);

    #pragma unroll 4
    for (int t = 0; t < T; t++) {
        CP_WAIT2();
        __syncthreads();
        compute(t);
        if (t + 1 < T) stsA(t + 1);
        if (t + 2 < T) ldgA(t + 2);
        if (t + 3 < T) cpB(t + 3);
        CP_COMMIT();
    }

    // --- epilogue ---
    const int mg0 = mt * 128 + wm * 64;
    const int ng0 = nt * 128 + wn * 32;
    float* Cz = Cg + (size_t)z * M * NPIX;
    float lsum = 0.f, lsq = 0.f;

    #pragma unroll
    for (int mf = 0; mf < 4; mf++) {
        const int r0 = mg0 + mf * 16 + gp;
        const float bv0 = EPI ? bias[r0]     : 0.f;
        const float bv1 = EPI ? bias[r0 + 8] : 0.f;
        #pragma unroll
        for (int nf = 0; nf < 4; nf++) {
            const int c0 = ng0 + nf * 8 + tq * 2;
            float2 v0, v1;
            v0.x = acc[mf][nf][0] + bv0;
            v0.y = acc[mf][nf][1] + bv0;
            v1.x = acc[mf][nf][2] + bv1;
            v1.y = acc[mf][nf][3] + bv1;
            if (EPI) {
                lsum += v0.x + v0.y + v1.x + v1.y;
                lsq  += v0.x * v0.x + v0.y * v0.y + v1.x * v1.x + v1.y * v1.y;
            }
            *(float2*)&Cz[(size_t)r0       * NPIX + c0] = v0;
            *(float2*)&Cz[(size_t)(r0 + 8) * NPIX + c0] = v1;
        }
    }

    if (EPI) {
        __shared__ float rs[8], rq[8];
        #pragma unroll
        for (int o = 16; o; o >>= 1) {
            lsum += __shfl_xor_sync(0xffffffffu, lsum, o);
            lsq  += __shfl_xor_sync(0xffffffffu, lsq,  o);
        }
        if (lane == 0) { rs[wid] = lsum; rq[wid] = lsq; }
        __syncthreads();
        if (tid == 0) {
            float s = 0.f, q = 0.f;
            #pragma unroll
            for (int w = 0; w < 8; w++) { s += rs[w]; q += rq[w]; }
            atomicAdd(&g_stats[2 * z + 0], s);
            atomicAdd(&g_stats[2 * z + 1], q);
        }
    }
}

// ---------------------------------------------------------------------------
// K2b: context partials, register-tiled 8x8 + fused exp-sum accumulation.
// ---------------------------------------------------------------------------
#define CTX_SMEM (8192 * 4)   // 32 KB

__global__ __launch_bounds__(256)
void k_ctx()
{
    extern __shared__ float sm[];
    float* ks = sm;                 // [32][65]
    float* vs = sm + 32 * 65;       // [32][65]

    const int ch = blockIdx.x, h = blockIdx.y, b = blockIdx.z;
    const int tid = threadIdx.x;
    const int g = tid >> 4, t16 = tid & 15;
    const int d0 = (t16 >> 2) * 8, e0 = (t16 & 3) * 8;
    const int bh = b * HEADS + h;

    const float* kbase = g_qkv + ((size_t)b * O3 + HID     + h * DH) * NPIX;
    const float* vbase = g_qkv + ((size_t)b * O3 + 2 * HID + h * DH) * NPIX;

    const int r = tid >> 3, c0 = (tid & 7) * 8;   // staging map

    float acc[8][8];
    #pragma unroll
    for (int i = 0; i < 8; i++)
        #pragma unroll
        for (int j = 0; j < 8; j++) acc[i][j] = 0.f;
    float esum = 0.f;

    #pragma unroll 1
    for (int tile = 0; tile < 8; ++tile) {
        const int nc = ch * 512 + tile * 64;
        const float4 k0 = *(const float4*)(kbase + (size_t)r * NPIX + nc + c0);
        const float4 k1 = *(const float4*)(kbase + (size_t)r * NPIX + nc + c0 + 4);
        const float4 v0 = *(const float4*)(vbase + (size_t)r * NPIX + nc + c0);
        const float4 v1 = *(const float4*)(vbase + (size_t)r * NPIX + nc + c0 + 4);
        float* kd = ks + r * 65 + c0;
        float* vd = vs + r * 65 + c0;
        float e0v = __expf(k0.x), e1v = __expf(k0.y);
        float e2v = __expf(k0.z), e3v = __expf(k0.w);
        float e4v = __expf(k1.x), e5v = __expf(k1.y);
        float e6v = __expf(k1.z), e7v = __expf(k1.w);
        kd[0] = e0v; kd[1] = e1v; kd[2] = e2v; kd[3] = e3v;
        kd[4] = e4v; kd[5] = e5v; kd[6] = e6v; kd[7] = e7v;
        esum += (e0v + e1v) + (e2v + e3v) + (e4v + e5v) + (e6v + e7v);
        vd[0] = v0.x; vd[1] = v0.y; vd[2] = v0.z; vd[3] = v0.w;
        vd[4] = v1.x; vd[5] = v1.y; vd[6] = v1.z; vd[7] = v1.w;
        __syncthreads();

        #pragma unroll
        for (int s = 0; s < 4; ++s) {
            const int j = g + s * 16;
            float ka[8], va[8];
            #pragma unroll
            for (int i = 0; i < 8; ++i) ka[i] = ks[(d0 + i) * 65 + j];
            #pragma unroll
            for (int i = 0; i < 8; ++i) va[i] = vs[(e0 + i) * 65 + j];
            #pragma unroll
            for (int i = 0; i < 8; ++i)
                #pragma unroll
                for (int jj = 0; jj < 8; ++jj)
                    acc[i][jj] += ka[i] * va[jj];
        }
        __syncthreads();
    }

    // per-row exp-sum: reduce across the 8 staging threads of row r
    #pragma unroll
    for (int o = 4; o; o >>= 1)
        esum += __shfl_xor_sync(0xffffffffu, esum, o);
    if ((tid & 7) == 0) atomicAdd(&g_ksum[bh * 32 + r], esum);

    // tree reduction over the 16 groups (red aliases staging region)
    float* red = sm;
    #pragma unroll
    for (int step = 8; step >= 1; step >>= 1) {
        if (g >= step && g < 2 * step) {
            float* dst = red + ((g - step) * 16 + t16) * 64;
            #pragma unroll
            for (int q = 0; q < 64; ++q) dst[q] = acc[q >> 3][q & 7];
        }
        __syncthreads();
        if (g < step) {
            const float* src = red + (g * 16 + t16) * 64;
            #pragma unroll
            for (int q = 0; q < 64; ++q) acc[q >> 3][q & 7] += src[q];
        }
        __syncthreads();
    }
    if (g == 0) {
        float* dst = g_ctx + bh * 1024;
        #pragma unroll
        for (int i = 0; i < 8; ++i)
            #pragma unroll
            for (int jj = 0; jj < 8; ++jj)
                atomicAdd(&dst[(d0 + i) * 32 + (e0 + jj)], acc[i][jj]);
    }
}

// ---------------------------------------------------------------------------
// K2c v2: q softmax + out = ctx^T q as a staged smem GEMM (NO per-thread
// indexed arrays -> no local-memory spill).
// Block (nt, h, b) covers 256 n-cols. Thread tid owns column n=tid during
// staging (exp + column sum in one register). Compute: warp w -> 4 ee rows,
// lane -> 8 n at stride 32. acc[4][8] = 32 regs.
// ---------------------------------------------------------------------------
__global__ __launch_bounds__(256)
void k_qout()
{
    __shared__ float qs[32][257];
    __shared__ float ctx[32][33];
    __shared__ float inv[32];

    const int nt = blockIdx.x, h = blockIdx.y, b = blockIdx.z;
    const int tid = threadIdx.x;
    const int bh = b * HEADS + h;

    if (tid < 32) inv[tid] = 1.f / g_ksum[bh * 32 + tid];
    __syncthreads();
    #pragma unroll
    for (int i = tid; i < 1024; i += 256)
        ctx[i >> 5][i & 31] = g_ctx[bh * 1024 + i] * inv[i >> 5];

    const float* qbase = g_qkv + ((size_t)b * O3 + h * DH) * NPIX + nt * 256;

    // stage: thread owns column tid; exp + sum in registers, normalize in smem
    float s = 0.f;
    #pragma unroll
    for (int d = 0; d < 32; d++) {
        const float e = __expf(qbase[(size_t)d * NPIX + tid]);
        qs[d][tid] = e;
        s += e;
    }
    const float iv = 0.17677669529663687f / s;   // scale = 32^-0.5
    #pragma unroll
    for (int d = 0; d < 32; d++) qs[d][tid] *= iv;
    __syncthreads();

    // compute 32x256 = ctx^T(32e x 32d) * qs(32d x 256n)
    const int w = tid >> 5, lane = tid & 31;   // w -> ee base w*4
    float acc[4][8];
    #pragma unroll
    for (int i = 0; i < 4; i++)
        #pragma unroll
        for (int j = 0; j < 8; j++) acc[i][j] = 0.f;

    #pragma unroll
    for (int d = 0; d < 32; d++) {
        float ca[4], qa[8];
        #pragma unroll
        for (int i = 0; i < 4; i++) ca[i] = ctx[d][w * 4 + i];   // broadcast
        #pragma unroll
        for (int j = 0; j < 8; j++) qa[j] = qs[d][lane + 32 * j];
        #pragma unroll
        for (int i = 0; i < 4; i++)
            #pragma unroll
            for (int j = 0; j < 8; j++)
                acc[i][j] += ca[i] * qa[j];
    }

    float* obase = g_attn + ((size_t)b * HID + h * DH) * NPIX + nt * 256;
    #pragma unroll
    for (int i = 0; i < 4; i++)
        #pragma unroll
        for (int j = 0; j < 8; j++)
            obase[(size_t)(w * 4 + i) * NPIX + lane + 32 * j] = acc[i][j];
}

// ---------------------------------------------------------------------------
// K4: in-place GroupNorm (per-batch stats) + per-channel affine
// ---------------------------------------------------------------------------
__global__ __launch_bounds__(256)
void k_gn(float* __restrict__ out,
          const float* __restrict__ gn_w,
          const float* __restrict__ gn_b)
{
    const size_t gid  = (size_t)blockIdx.x * blockDim.x + threadIdx.x;
    const size_t base = gid * 4;
    const int b = (int)(base >> 20);
    const int c = (int)((base >> 12) & 255);

    const float invN = 1.f / (256.f * 4096.f);
    const float mean = g_stats[2 * b + 0] * invN;
    const float var  = g_stats[2 * b + 1] * invN - mean * mean;
    const float r    = rsqrtf(var + EPS);
    const float w    = gn_w[c] * r;
    const float bb   = gn_b[c] - mean * w;

    float4 v = *(float4*)&out[base];
    v.x = v.x * w + bb;
    v.y = v.y * w + bb;
    v.z = v.z * w + bb;
    v.w = v.w * w + bb;
    *(float4*)&out[base] = v;
}

// ---------------------------------------------------------------------------
// Launch
// ---------------------------------------------------------------------------
extern "C" void kernel_launch(void* const* d_in, const int* in_sizes, int n_in,
                              void* d_out, int out_size)
{
    const float* x     = (const float*)d_in[0];
    const float* w_qkv = (const float*)d_in[1];
    const float* w_out = (const float*)d_in[2];
    const float* b_out = (const float*)d_in[3];
    const float* gn_w  = (const float*)d_in[4];
    const float* gn_b  = (const float*)d_in[5];
    float* out = (float*)d_out;

    float *p_qkv, *p_attn;
    cudaGetSymbolAddress((void**)&p_qkv,  g_qkv);
    cudaGetSymbolAddress((void**)&p_attn, g_attn);

    cudaFuncSetAttribute(k_mma<CIN, O3, false>,
                         cudaFuncAttributeMaxDynamicSharedMemorySize, MMA_SMEM);
    cudaFuncSetAttribute(k_mma<HID, CIN, true>,
                         cudaFuncAttributeMaxDynamicSharedMemorySize, MMA_SMEM);
    cudaFuncSetAttribute(k_ctx,
                         cudaFuncAttributeMaxDynamicSharedMemorySize, CTX_SMEM);

    // K0: zero ctx + ksum + stats
    k_zero<<<(ZERO_N + 255) / 256, 256>>>();

    // K1: QKV projection  [384,256] x [256,4096] per batch (tf32 HMMA)
    k_mma<CIN, O3, false>
        <<<dim3(O3 / 128, NPIX / 128, BATCH), 256, MMA_SMEM>>>(w_qkv, x, p_qkv, nullptr);

    // K2: attention core
    k_ctx <<<dim3(8, HEADS, BATCH), 256, CTX_SMEM>>>();
    k_qout<<<dim3(NPIX / 256, HEADS, BATCH), 256>>>();

    // K3: output projection + bias + stats  [256,128] x [128,4096] per batch
    k_mma<HID, CIN, true>
        <<<dim3(CIN / 128, NPIX / 128, BATCH), 256, MMA_SMEM>>>(w_out, p_attn, out, b_out);

    // K4: GroupNorm normalize in place
    k_gn<<<(BATCH * CIN * NPIX / 4) / 256, 256>>>(out, gn_w, gn_b);
}

// round 11
// speedup vs baseline: 2.2818x; 1.2649x over previous
#include <cuda_runtime.h>
#include <cuda_fp16.h>
#include <cstdint>

// Problem constants
#define BATCH   32
#define CIN     256
#define NPIX    4096          // 64*64
#define HEADS   4
#define DH      32
#define HID     128           // HEADS*DH
#define O3      384           // 3*HID
#define EPS     1e-5f

// ---------------------------------------------------------------------------
// Scratch (device globals: allocation-free)
// ---------------------------------------------------------------------------
__device__ float    g_qkv [(size_t)BATCH * O3 * NPIX];        // 201 MB fp32
__device__ uint32_t g_attn[(size_t)BATCH * (HID/2) * NPIX];   //  34 MB packed fp16 k-pairs
__device__ float    g_stats[BATCH * 2];
__device__ float    g_ksum [BATCH * HEADS * 32];
__device__ float    g_ctx  [BATCH * HEADS * 32 * 32];

#define N_CTX  (BATCH * HEADS * 32 * 32)
#define N_KSUM (BATCH * HEADS * 32)
#define ZERO_N (N_CTX + N_KSUM + BATCH * 2)
__global__ void k_zero() {
    const int i = blockIdx.x * blockDim.x + threadIdx.x;
    if (i < N_CTX) g_ctx[i] = 0.f;
    else if (i < N_CTX + N_KSUM) g_ksum[i - N_CTX] = 0.f;
    else if (i < ZERO_N) g_stats[i - N_CTX - N_KSUM] = 0.f;
}

// ---------------------------------------------------------------------------
// helpers (sm_80-baseline)
// ---------------------------------------------------------------------------
__device__ __forceinline__ uint32_t pack2(float lo, float hi) {
    __half2 h = __floats2half2_rn(lo, hi);
    return *reinterpret_cast<uint32_t*>(&h);
}
__device__ __forceinline__ void mma_f16(float c[4],
                                        const uint32_t a[4],
                                        const uint32_t b[2]) {
    asm volatile(
        "mma.sync.aligned.m16n8k16.row.col.f32.f16.f16.f32 "
        "{%0,%1,%2,%3}, {%4,%5,%6,%7}, {%8,%9}, {%0,%1,%2,%3};"
        : "+f"(c[0]), "+f"(c[1]), "+f"(c[2]), "+f"(c[3])
        : "r"(a[0]), "r"(a[1]), "r"(a[2]), "r"(a[3]),
          "r"(b[0]), "r"(b[1]));
}

// ---------------------------------------------------------------------------
// fp16 tensor-core GEMM:  C[z][M][4096] = A[M,K] * B[z][K,4096]  (+bias,+stats)
// CTA tile 128x128, BK=16 (one m16n8k16 k-step), 8 warps (2m x 4n),
// warp tile 64x32 -> 16 MMA/warp/iter.
// smem: As [2][128 m][8 kw] word-swizzled by m&4; Bs [2][8 kw][128 n]
// col-swizzled by (kw&3)*8. Both fp16x2-packed along k. 16 KB total.
// BPK=false: B is fp32 gmem (cvt at staging). BPK=true: B pre-packed fp16.
// ---------------------------------------------------------------------------
template<int K, int M, bool EPI, bool BPK>
__global__ __launch_bounds__(256)
void k_mma(const float* __restrict__ A, const void* __restrict__ Bg_,
           float* __restrict__ Cg, const float* __restrict__ bias)
{
    __shared__ uint32_t As[2][128][8];
    __shared__ uint32_t Bs[2][8][128];

    const int tid  = threadIdx.x, lane = tid & 31, wid = tid >> 5;
    const int wm   = wid >> 2, wn = wid & 3;
    const int tq   = lane & 3, gp = lane >> 2;
    const int mt   = blockIdx.x, nt = blockIdx.y, z = blockIdx.z;

    const float* Ap = A + (size_t)mt * 128 * K;
    const float*    Bpf = BPK ? nullptr
                     : (const float*)Bg_ + (size_t)z * K * NPIX + nt * 128;
    const uint32_t* Bpp = BPK
                     ? (const uint32_t*)Bg_ + (size_t)z * (K/2) * NPIX + nt * 128
                     : nullptr;

    // A loader: row am, word base akw (4 words = 8 k)
    const int am  = tid & 127, akw = (tid >> 7) * 4;
    // B loader: word-row bkw (0..7), col base n0 (4 words)
    const int bkw = tid >> 5;
    const int bn0 = (lane) * 4;

    float acc[4][4][4];
    #pragma unroll
    for (int i = 0; i < 4; i++)
        #pragma unroll
        for (int j = 0; j < 4; j++)
            #pragma unroll
            for (int r = 0; r < 4; r++) acc[i][j][r] = 0.f;

    float4 ra[2];      // A prefetch regs (8 fp32)
    float4 rbf[2];     // B prefetch regs (fp32 mode)
    uint4  rbp;        // B prefetch regs (packed mode)

    auto ldgA = [&](int t) {
        #pragma unroll
        for (int j = 0; j < 2; j++)
            ra[j] = *(const float4*)(Ap + (size_t)am * K + t * 16 + akw * 2 + j * 4);
    };
    auto stsA = [&](int t) {
        const int buf = t & 1;
        uint32_t w0 = pack2(ra[0].x, ra[0].y);
        uint32_t w1 = pack2(ra[0].z, ra[0].w);
        uint32_t w2 = pack2(ra[1].x, ra[1].y);
        uint32_t w3 = pack2(ra[1].z, ra[1].w);
        // words akw..akw+3, XOR by (am&4) keeps them contiguous (0..3 <-> 4..7)
        *(uint4*)&As[buf][am][akw ^ (am & 4)] = make_uint4(w0, w1, w2, w3);
    };
    auto ldgB = [&](int t) {
        if (BPK) {
            rbp = *(const uint4*)(Bpp + (size_t)(t * 8 + bkw) * NPIX + bn0);
        } else {
            rbf[0] = *(const float4*)(Bpf + (size_t)(t * 16 + 2 * bkw    ) * NPIX + bn0);
            rbf[1] = *(const float4*)(Bpf + (size_t)(t * 16 + 2 * bkw + 1) * NPIX + bn0);
        }
    };
    auto stsB = [&](int t) {
        const int buf = t & 1;
        const int col = bn0 ^ ((bkw & 3) * 8);
        if (BPK) {
            *(uint4*)&Bs[buf][bkw][col] = rbp;
        } else {
            *(uint4*)&Bs[buf][bkw][col] = make_uint4(
                pack2(rbf[0].x, rbf[1].x), pack2(rbf[0].y, rbf[1].y),
                pack2(rbf[0].z, rbf[1].z), pack2(rbf[0].w, rbf[1].w));
        }
    };
    auto compute = [&](int t) {
        const int buf = t & 1;
        uint32_t bf[4][2];
        #pragma unroll
        for (int nf = 0; nf < 4; nf++) {
            const int col = (wn * 32 + nf * 8 + gp) ^ (tq * 8);
            bf[nf][0] = Bs[buf][tq    ][col];
            bf[nf][1] = Bs[buf][tq + 4][col];
        }
        #pragma unroll
        for (int mf = 0; mf < 4; mf++) {
            uint32_t af[4];
            const int m0 = wm * 64 + mf * 16 + gp;   // m0&4 == gp&4
            const int s0 = (m0 & 4);
            af[0] = As[buf][m0    ][tq ^ s0];
            af[1] = As[buf][m0 + 8][tq ^ s0];
            af[2] = As[buf][m0    ][(tq + 4) ^ s0];
            af[3] = As[buf][m0 + 8][(tq + 4) ^ s0];
            #pragma unroll
            for (int nf = 0; nf < 4; nf++)
                mma_f16(acc[mf][nf], af, bf[nf]);
        }
    };

    constexpr int T = K / 16;

    ldgA(0); ldgB(0);
    stsA(0); stsB(0);
    ldgA(1); ldgB(1);
    __syncthreads();

    #pragma unroll 1
    for (int t = 0; t < T; t++) {
        compute(t);
        if (t + 1 < T) { stsA(t + 1); stsB(t + 1); }   // other buffer: safe
        if (t + 2 < T) { ldgA(t + 2); ldgB(t + 2); }
        __syncthreads();
    }

    // --- epilogue (same fragment layout as m16n8k8: c0/c1 row gp, c2/c3 gp+8)
    const int mg0 = mt * 128 + wm * 64;
    const int ng0 = nt * 128 + wn * 32;
    float* Cz = Cg + (size_t)z * M * NPIX;
    float lsum = 0.f, lsq = 0.f;

    #pragma unroll
    for (int mf = 0; mf < 4; mf++) {
        const int r0 = mg0 + mf * 16 + gp;
        const float bv0 = EPI ? bias[r0]     : 0.f;
        const float bv1 = EPI ? bias[r0 + 8] : 0.f;
        #pragma unroll
        for (int nf = 0; nf < 4; nf++) {
            const int c0 = ng0 + nf * 8 + tq * 2;
            float2 v0, v1;
            v0.x = acc[mf][nf][0] + bv0;
            v0.y = acc[mf][nf][1] + bv0;
            v1.x = acc[mf][nf][2] + bv1;
            v1.y = acc[mf][nf][3] + bv1;
            if (EPI) {
                lsum += v0.x + v0.y + v1.x + v1.y;
                lsq  += v0.x * v0.x + v0.y * v0.y + v1.x * v1.x + v1.y * v1.y;
            }
            *(float2*)&Cz[(size_t)r0       * NPIX + c0] = v0;
            *(float2*)&Cz[(size_t)(r0 + 8) * NPIX + c0] = v1;
        }
    }

    if (EPI) {
        __shared__ float rs[8], rq[8];
        #pragma unroll
        for (int o = 16; o; o >>= 1) {
            lsum += __shfl_xor_sync(0xffffffffu, lsum, o);
            lsq  += __shfl_xor_sync(0xffffffffu, lsq,  o);
        }
        if (lane == 0) { rs[wid] = lsum; rq[wid] = lsq; }
        __syncthreads();
        if (tid == 0) {
            float s = 0.f, q = 0.f;
            #pragma unroll
            for (int w = 0; w < 8; w++) { s += rs[w]; q += rq[w]; }
            atomicAdd(&g_stats[2 * z + 0], s);
            atomicAdd(&g_stats[2 * z + 1], q);
        }
    }
}

// ---------------------------------------------------------------------------
// K2b: context partials, register-tiled 8x8 + fused exp-sum (unchanged)
// ---------------------------------------------------------------------------
#define CTX_SMEM (8192 * 4)   // 32 KB

__global__ __launch_bounds__(256)
void k_ctx()
{
    extern __shared__ float sm[];
    float* ks = sm;                 // [32][65]
    float* vs = sm + 32 * 65;       // [32][65]

    const int ch = blockIdx.x, h = blockIdx.y, b = blockIdx.z;
    const int tid = threadIdx.x;
    const int g = tid >> 4, t16 = tid & 15;
    const int d0 = (t16 >> 2) * 8, e0 = (t16 & 3) * 8;
    const int bh = b * HEADS + h;

    const float* kbase = g_qkv + ((size_t)b * O3 + HID     + h * DH) * NPIX;
    const float* vbase = g_qkv + ((size_t)b * O3 + 2 * HID + h * DH) * NPIX;

    const int r = tid >> 3, c0 = (tid & 7) * 8;

    float acc[8][8];
    #pragma unroll
    for (int i = 0; i < 8; i++)
        #pragma unroll
        for (int j = 0; j < 8; j++) acc[i][j] = 0.f;
    float esum = 0.f;

    #pragma unroll 1
    for (int tile = 0; tile < 8; ++tile) {
        const int nc = ch * 512 + tile * 64;
        const float4 k0 = *(const float4*)(kbase + (size_t)r * NPIX + nc + c0);
        const float4 k1 = *(const float4*)(kbase + (size_t)r * NPIX + nc + c0 + 4);
        const float4 v0 = *(const float4*)(vbase + (size_t)r * NPIX + nc + c0);
        const float4 v1 = *(const float4*)(vbase + (size_t)r * NPIX + nc + c0 + 4);
        float* kd = ks + r * 65 + c0;
        float* vd = vs + r * 65 + c0;
        float e0v = __expf(k0.x), e1v = __expf(k0.y);
        float e2v = __expf(k0.z), e3v = __expf(k0.w);
        float e4v = __expf(k1.x), e5v = __expf(k1.y);
        float e6v = __expf(k1.z), e7v = __expf(k1.w);
        kd[0] = e0v; kd[1] = e1v; kd[2] = e2v; kd[3] = e3v;
        kd[4] = e4v; kd[5] = e5v; kd[6] = e6v; kd[7] = e7v;
        esum += (e0v + e1v) + (e2v + e3v) + (e4v + e5v) + (e6v + e7v);
        vd[0] = v0.x; vd[1] = v0.y; vd[2] = v0.z; vd[3] = v0.w;
        vd[4] = v1.x; vd[5] = v1.y; vd[6] = v1.z; vd[7] = v1.w;
        __syncthreads();

        #pragma unroll
        for (int s = 0; s < 4; ++s) {
            const int j = g + s * 16;
            float ka[8], va[8];
            #pragma unroll
            for (int i = 0; i < 8; ++i) ka[i] = ks[(d0 + i) * 65 + j];
            #pragma unroll
            for (int i = 0; i < 8; ++i) va[i] = vs[(e0 + i) * 65 + j];
            #pragma unroll
            for (int i = 0; i < 8; ++i)
                #pragma unroll
                for (int jj = 0; jj < 8; ++jj)
                    acc[i][jj] += ka[i] * va[jj];
        }
        __syncthreads();
    }

    #pragma unroll
    for (int o = 4; o; o >>= 1)
        esum += __shfl_xor_sync(0xffffffffu, esum, o);
    if ((tid & 7) == 0) atomicAdd(&g_ksum[bh * 32 + r], esum);

    float* red = sm;
    #pragma unroll
    for (int step = 8; step >= 1; step >>= 1) {
        if (g >= step && g < 2 * step) {
            float* dst = red + ((g - step) * 16 + t16) * 64;
            #pragma unroll
            for (int q = 0; q < 64; ++q) dst[q] = acc[q >> 3][q & 7];
        }
        __syncthreads();
        if (g < step) {
            const float* src = red + (g * 16 + t16) * 64;
            #pragma unroll
            for (int q = 0; q < 64; ++q) acc[q >> 3][q & 7] += src[q];
        }
        __syncthreads();
    }
    if (g == 0) {
        float* dst = g_ctx + bh * 1024;
        #pragma unroll
        for (int i = 0; i < 8; ++i)
            #pragma unroll
            for (int jj = 0; jj < 8; ++jj)
                atomicAdd(&dst[(d0 + i) * 32 + (e0 + jj)], acc[i][jj]);
    }
}

// ---------------------------------------------------------------------------
// K2c: q softmax + out = ctx^T q (staged smem GEMM, no spills).
// Output: g_attn packed fp16 k-pairs [hid/2][npix] per batch, ready for the
// out-proj GEMM's packed-B loader.
// ---------------------------------------------------------------------------
__global__ __launch_bounds__(256)
void k_qout()
{
    __shared__ float qs[32][257];
    __shared__ float ctx[32][33];
    __shared__ float inv[32];

    const int nt = blockIdx.x, h = blockIdx.y, b = blockIdx.z;
    const int tid = threadIdx.x;
    const int bh = b * HEADS + h;

    if (tid < 32) inv[tid] = 1.f / g_ksum[bh * 32 + tid];
    __syncthreads();
    #pragma unroll
    for (int i = tid; i < 1024; i += 256)
        ctx[i >> 5][i & 31] = g_ctx[bh * 1024 + i] * inv[i >> 5];

    const float* qbase = g_qkv + ((size_t)b * O3 + h * DH) * NPIX + nt * 256;

    float s = 0.f;
    #pragma unroll
    for (int d = 0; d < 32; d++) {
        const float e = __expf(qbase[(size_t)d * NPIX + tid]);
        qs[d][tid] = e;
        s += e;
    }
    const float iv = 0.17677669529663687f / s;   // scale = 32^-0.5
    #pragma unroll
    for (int d = 0; d < 32; d++) qs[d][tid] *= iv;
    __syncthreads();

    const int w = tid >> 5, lane = tid & 31;
    float acc[4][8];
    #pragma unroll
    for (int i = 0; i < 4; i++)
        #pragma unroll
        for (int j = 0; j < 8; j++) acc[i][j] = 0.f;

    #pragma unroll
    for (int d = 0; d < 32; d++) {
        float ca[4], qa[8];
        #pragma unroll
        for (int i = 0; i < 4; i++) ca[i] = ctx[d][w * 4 + i];
        #pragma unroll
        for (int j = 0; j < 8; j++) qa[j] = qs[d][lane + 32 * j];
        #pragma unroll
        for (int i = 0; i < 4; i++)
            #pragma unroll
            for (int j = 0; j < 8; j++)
                acc[i][j] += ca[i] * qa[j];
    }

    // pack (hid, hid+1) fp16 pairs: rows w*4+i -> kw = h*16 + w*2 + i/2
    uint32_t* obase = g_attn + ((size_t)b * (HID/2)) * NPIX + nt * 256;
    const int kw0 = h * 16 + w * 2;
    #pragma unroll
    for (int j = 0; j < 8; j++) {
        const int n = lane + 32 * j;
        obase[(size_t)kw0       * NPIX + n] = pack2(acc[0][j], acc[1][j]);
        obase[(size_t)(kw0 + 1) * NPIX + n] = pack2(acc[2][j], acc[3][j]);
    }
}

// ---------------------------------------------------------------------------
// K4: in-place GroupNorm (per-batch stats) + per-channel affine
// ---------------------------------------------------------------------------
__global__ __launch_bounds__(256)
void k_gn(float* __restrict__ out,
          const float* __restrict__ gn_w,
          const float* __restrict__ gn_b)
{
    const size_t gid  = (size_t)blockIdx.x * blockDim.x + threadIdx.x;
    const size_t base = gid * 4;
    const int b = (int)(base >> 20);
    const int c = (int)((base >> 12) & 255);

    const float invN = 1.f / (256.f * 4096.f);
    const float mean = g_stats[2 * b + 0] * invN;
    const float var  = g_stats[2 * b + 1] * invN - mean * mean;
    const float r    = rsqrtf(var + EPS);
    const float w    = gn_w[c] * r;
    const float bb   = gn_b[c] - mean * w;

    float4 v = *(float4*)&out[base];
    v.x = v.x * w + bb;
    v.y = v.y * w + bb;
    v.z = v.z * w + bb;
    v.w = v.w * w + bb;
    *(float4*)&out[base] = v;
}

// ---------------------------------------------------------------------------
// Launch
// ---------------------------------------------------------------------------
extern "C" void kernel_launch(void* const* d_in, const int* in_sizes, int n_in,
                              void* d_out, int out_size)
{
    const float* x     = (const float*)d_in[0];
    const float* w_qkv = (const float*)d_in[1];
    const float* w_out = (const float*)d_in[2];
    const float* b_out = (const float*)d_in[3];
    const float* gn_w  = (const float*)d_in[4];
    const float* gn_b  = (const float*)d_in[5];
    float* out = (float*)d_out;

    float    *p_qkv;
    uint32_t *p_attn;
    cudaGetSymbolAddress((void**)&p_qkv,  g_qkv);
    cudaGetSymbolAddress((void**)&p_attn, g_attn);

    cudaFuncSetAttribute(k_ctx,
                         cudaFuncAttributeMaxDynamicSharedMemorySize, CTX_SMEM);

    // K0: zero ctx + ksum + stats
    k_zero<<<(ZERO_N + 255) / 256, 256>>>();

    // K1: QKV projection  [384,256] x [256,4096] per batch (fp16 HMMA)
    k_mma<CIN, O3, false, false>
        <<<dim3(O3 / 128, NPIX / 128, BATCH), 256>>>(w_qkv, x, p_qkv, nullptr);

    // K2: attention core
    k_ctx <<<dim3(8, HEADS, BATCH), 256, CTX_SMEM>>>();
    k_qout<<<dim3(NPIX / 256, HEADS, BATCH), 256>>>();

    // K3: output projection + bias + stats  (B = packed fp16 attn)
    k_mma<HID, CIN, true, true>
        <<<dim3(CIN / 128, NPIX / 128, BATCH), 256>>>(w_out, p_attn, out, b_out);

    // K4: GroupNorm normalize in place
    k_gn<<<(BATCH * CIN * NPIX / 4) / 256, 256>>>(out, gn_w, gn_b);
}

// round 12
// speedup vs baseline: 2.6464x; 1.1598x over previous
#include <cuda_runtime.h>
#include <cuda_fp16.h>
#include <cstdint>

// Problem constants
#define BATCH   32
#define CIN     256
#define NPIX    4096          // 64*64
#define HEADS   4
#define DH      32
#define HID     128           // HEADS*DH
#define O3      384           // 3*HID
#define EPS     1e-5f
#define PW      (NPIX / 2)    // words per row of packed fp16 (2048)

// ---------------------------------------------------------------------------
// Scratch (device globals: allocation-free)
// ---------------------------------------------------------------------------
__device__ uint32_t g_qkvh[(size_t)BATCH * O3 * PW];          // 100 MB: exp(q),exp(k),v fp16 pairs (along n)
__device__ uint32_t g_attn[(size_t)BATCH * (HID/2) * NPIX];   //  34 MB: packed fp16 k-pairs (along hid)
__device__ float    g_stats[BATCH * 2];
__device__ float    g_ksum [BATCH * HEADS * 32];
__device__ float    g_ctx  [BATCH * HEADS * 32 * 32];

#define N_CTX  (BATCH * HEADS * 32 * 32)
#define N_KSUM (BATCH * HEADS * 32)
#define ZERO_N (N_CTX + N_KSUM + BATCH * 2)
__global__ void k_zero() {
    const int i = blockIdx.x * blockDim.x + threadIdx.x;
    if (i < N_CTX) g_ctx[i] = 0.f;
    else if (i < N_CTX + N_KSUM) g_ksum[i - N_CTX] = 0.f;
    else if (i < ZERO_N) g_stats[i - N_CTX - N_KSUM] = 0.f;
}

// ---------------------------------------------------------------------------
// helpers (sm_80-baseline)
// ---------------------------------------------------------------------------
__device__ __forceinline__ uint32_t pack2(float lo, float hi) {
    __half2 h = __floats2half2_rn(lo, hi);
    return *reinterpret_cast<uint32_t*>(&h);
}
__device__ __forceinline__ void mma_f16(float c[4],
                                        const uint32_t a[4],
                                        const uint32_t b[2]) {
    asm volatile(
        "mma.sync.aligned.m16n8k16.row.col.f32.f16.f16.f32 "
        "{%0,%1,%2,%3}, {%4,%5,%6,%7}, {%8,%9}, {%0,%1,%2,%3};"
        : "+f"(c[0]), "+f"(c[1]), "+f"(c[2]), "+f"(c[3])
        : "r"(a[0]), "r"(a[1]), "r"(a[2]), "r"(a[3]),
          "r"(b[0]), "r"(b[1]));
}

// ---------------------------------------------------------------------------
// fp16 tensor-core GEMM:  C[z][M][4096] = A[M,K] * B[z][K,4096]
// CTA tile 128x128, BK=16, 8 warps (2m x 4n), warp tile 64x32.
// MODE 0 (QKV): output packed fp16 pairs along n; exp() applied to q,k tiles
//               (mt<2); k-row exp-sums atomically accumulated into g_ksum.
// MODE 1 (OUT): fp32 output + bias + per-batch sum/sumsq stats.
// BPK: B is pre-packed fp16 (true) or fp32 (false, cvt at staging).
// ---------------------------------------------------------------------------
template<int K, int M, int MODE, bool BPK>
__global__ __launch_bounds__(256)
void k_mma(const float* __restrict__ A, const void* __restrict__ Bg_,
           void* __restrict__ Cg, const float* __restrict__ bias)
{
    __shared__ uint32_t As[2][128][8];
    __shared__ uint32_t Bs[2][8][128];

    const int tid  = threadIdx.x, lane = tid & 31, wid = tid >> 5;
    const int wm   = wid >> 2, wn = wid & 3;
    const int tq   = lane & 3, gp = lane >> 2;
    const int mt   = blockIdx.x, nt = blockIdx.y, z = blockIdx.z;

    const float* Ap = A + (size_t)mt * 128 * K;
    const float*    Bpf = BPK ? nullptr
                     : (const float*)Bg_ + (size_t)z * K * NPIX + nt * 128;
    const uint32_t* Bpp = BPK
                     ? (const uint32_t*)Bg_ + (size_t)z * (K/2) * NPIX + nt * 128
                     : nullptr;

    const int am  = tid & 127, akw = (tid >> 7) * 4;
    const int bkw = tid >> 5;
    const int bn0 = lane * 4;

    float acc[4][4][4];
    #pragma unroll
    for (int i = 0; i < 4; i++)
        #pragma unroll
        for (int j = 0; j < 4; j++)
            #pragma unroll
            for (int r = 0; r < 4; r++) acc[i][j][r] = 0.f;

    float4 ra[2];
    float4 rbf[2];
    uint4  rbp;

    auto ldgA = [&](int t) {
        #pragma unroll
        for (int j = 0; j < 2; j++)
            ra[j] = *(const float4*)(Ap + (size_t)am * K + t * 16 + akw * 2 + j * 4);
    };
    auto stsA = [&](int t) {
        const int buf = t & 1;
        uint32_t w0 = pack2(ra[0].x, ra[0].y);
        uint32_t w1 = pack2(ra[0].z, ra[0].w);
        uint32_t w2 = pack2(ra[1].x, ra[1].y);
        uint32_t w3 = pack2(ra[1].z, ra[1].w);
        *(uint4*)&As[buf][am][akw ^ (am & 4)] = make_uint4(w0, w1, w2, w3);
    };
    auto ldgB = [&](int t) {
        if (BPK) {
            rbp = *(const uint4*)(Bpp + (size_t)(t * 8 + bkw) * NPIX + bn0);
        } else {
            rbf[0] = *(const float4*)(Bpf + (size_t)(t * 16 + 2 * bkw    ) * NPIX + bn0);
            rbf[1] = *(const float4*)(Bpf + (size_t)(t * 16 + 2 * bkw + 1) * NPIX + bn0);
        }
    };
    auto stsB = [&](int t) {
        const int buf = t & 1;
        const int col = bn0 ^ ((bkw & 3) * 8);
        if (BPK) {
            *(uint4*)&Bs[buf][bkw][col] = rbp;
        } else {
            *(uint4*)&Bs[buf][bkw][col] = make_uint4(
                pack2(rbf[0].x, rbf[1].x), pack2(rbf[0].y, rbf[1].y),
                pack2(rbf[0].z, rbf[1].z), pack2(rbf[0].w, rbf[1].w));
        }
    };
    auto compute = [&](int t) {
        const int buf = t & 1;
        uint32_t bf[4][2];
        #pragma unroll
        for (int nf = 0; nf < 4; nf++) {
            const int col = (wn * 32 + nf * 8 + gp) ^ (tq * 8);
            bf[nf][0] = Bs[buf][tq    ][col];
            bf[nf][1] = Bs[buf][tq + 4][col];
        }
        #pragma unroll
        for (int mf = 0; mf < 4; mf++) {
            uint32_t af[4];
            const int m0 = wm * 64 + mf * 16 + gp;
            const int s0 = (m0 & 4);
            af[0] = As[buf][m0    ][tq ^ s0];
            af[1] = As[buf][m0 + 8][tq ^ s0];
            af[2] = As[buf][m0    ][(tq + 4) ^ s0];
            af[3] = As[buf][m0 + 8][(tq + 4) ^ s0];
            #pragma unroll
            for (int nf = 0; nf < 4; nf++)
                mma_f16(acc[mf][nf], af, bf[nf]);
        }
    };

    constexpr int T = K / 16;

    ldgA(0); ldgB(0);
    stsA(0); stsB(0);
    ldgA(1); ldgB(1);
    __syncthreads();

    #pragma unroll 1
    for (int t = 0; t < T; t++) {
        compute(t);
        if (t + 1 < T) { stsA(t + 1); stsB(t + 1); }
        if (t + 2 < T) { ldgA(t + 2); ldgB(t + 2); }
        __syncthreads();
    }

    const int mg0 = mt * 128 + wm * 64;
    const int ng0 = nt * 128 + wn * 32;

    if (MODE == 0) {
        // --- QKV epilogue: exp (q,k) + pack fp16 pairs along n + ksum ---
        uint32_t* Cw = (uint32_t*)Cg + (size_t)z * M * PW;
        #pragma unroll
        for (int mf = 0; mf < 4; mf++) {
            const int r0 = mg0 + mf * 16 + gp;
            float s0 = 0.f, s1 = 0.f;
            #pragma unroll
            for (int nf = 0; nf < 4; nf++) {
                const int wc = (ng0 >> 1) + nf * 4 + tq;
                float a0 = acc[mf][nf][0], a1 = acc[mf][nf][1];
                float a2 = acc[mf][nf][2], a3 = acc[mf][nf][3];
                if (mt < 2) {
                    a0 = __expf(a0); a1 = __expf(a1);
                    a2 = __expf(a2); a3 = __expf(a3);
                }
                s0 += a0 + a1; s1 += a2 + a3;
                Cw[(size_t)r0      * PW + wc] = pack2(a0, a1);
                Cw[(size_t)(r0+8)  * PW + wc] = pack2(a2, a3);
            }
            if (mt == 1) {   // k rows: accumulate exp-sums
                s0 += __shfl_xor_sync(0xffffffffu, s0, 1);
                s0 += __shfl_xor_sync(0xffffffffu, s0, 2);
                s1 += __shfl_xor_sync(0xffffffffu, s1, 1);
                s1 += __shfl_xor_sync(0xffffffffu, s1, 2);
                if (tq == 0) {
                    const int rk  = wm * 64 + mf * 16 + gp;
                    const int rk8 = rk + 8;
                    atomicAdd(&g_ksum[(z * HEADS + (rk  >> 5)) * 32 + (rk  & 31)], s0);
                    atomicAdd(&g_ksum[(z * HEADS + (rk8 >> 5)) * 32 + (rk8 & 31)], s1);
                }
            }
        }
    } else {
        // --- OUT epilogue: fp32 + bias + stats ---
        float* Cz = (float*)Cg + (size_t)z * M * NPIX;
        float lsum = 0.f, lsq = 0.f;
        #pragma unroll
        for (int mf = 0; mf < 4; mf++) {
            const int r0 = mg0 + mf * 16 + gp;
            const float bv0 = bias[r0];
            const float bv1 = bias[r0 + 8];
            #pragma unroll
            for (int nf = 0; nf < 4; nf++) {
                const int c0 = ng0 + nf * 8 + tq * 2;
                float2 v0, v1;
                v0.x = acc[mf][nf][0] + bv0;
                v0.y = acc[mf][nf][1] + bv0;
                v1.x = acc[mf][nf][2] + bv1;
                v1.y = acc[mf][nf][3] + bv1;
                lsum += v0.x + v0.y + v1.x + v1.y;
                lsq  += v0.x * v0.x + v0.y * v0.y + v1.x * v1.x + v1.y * v1.y;
                *(float2*)&Cz[(size_t)r0       * NPIX + c0] = v0;
                *(float2*)&Cz[(size_t)(r0 + 8) * NPIX + c0] = v1;
            }
        }
        __shared__ float rs[8], rq[8];
        #pragma unroll
        for (int o = 16; o; o >>= 1) {
            lsum += __shfl_xor_sync(0xffffffffu, lsum, o);
            lsq  += __shfl_xor_sync(0xffffffffu, lsq,  o);
        }
        if (lane == 0) { rs[wid] = lsum; rq[wid] = lsq; }
        __syncthreads();
        if (tid == 0) {
            float s = 0.f, q = 0.f;
            #pragma unroll
            for (int w = 0; w < 8; w++) { s += rs[w]; q += rq[w]; }
            atomicAdd(&g_stats[2 * z + 0], s);
            atomicAdd(&g_stats[2 * z + 1], q);
        }
    }
}

// ---------------------------------------------------------------------------
// K2b v3: ctx = expk @ v^T as pure fp16 MMA with gmem-direct fragments.
// Block (nt: 1024 px, h, b), 8 warps x 128 px (8 k-steps of 16).
// Per k-step, per lane: A frag = expk rows {dm+gp, dm+gp+8} words {tq, tq+4};
// B frag = v row {en+gp} words {tq, tq+4}. 16 LDG.32 + 8 MMA.
// No exp (precomputed), no staging barriers. Per-warp partials -> smem ->
// 8-way reduce -> atomicAdd.
// ---------------------------------------------------------------------------
__global__ __launch_bounds__(256)
void k_ctx()
{
    __shared__ float red[8][32][33];

    const int nt = blockIdx.x, h = blockIdx.y, b = blockIdx.z;
    const int tid = threadIdx.x, lane = tid & 31, w = tid >> 5;
    const int gp = lane >> 2, tq = lane & 3;
    const int bh = b * HEADS + h;

    const uint32_t* kw = g_qkvh + ((size_t)b * O3 + HID     + h * DH) * PW;
    const uint32_t* vw = g_qkvh + ((size_t)b * O3 + 2 * HID + h * DH) * PW;
    const int wb0 = nt * 512 + w * 64;   // word offset of this warp's slice

    float acc[2][4][4];
    #pragma unroll
    for (int i = 0; i < 2; i++)
        #pragma unroll
        for (int j = 0; j < 4; j++)
            #pragma unroll
            for (int r = 0; r < 4; r++) acc[i][j][r] = 0.f;

    #pragma unroll
    for (int kk = 0; kk < 8; kk++) {
        const int w0 = wb0 + kk * 8 + tq, w1 = w0 + 4;
        uint32_t af[2][4], bf[4][2];
        #pragma unroll
        for (int m2 = 0; m2 < 2; m2++) {
            const int dm = m2 * 16;
            af[m2][0] = kw[(size_t)(dm + gp    ) * PW + w0];
            af[m2][1] = kw[(size_t)(dm + gp + 8) * PW + w0];
            af[m2][2] = kw[(size_t)(dm + gp    ) * PW + w1];
            af[m2][3] = kw[(size_t)(dm + gp + 8) * PW + w1];
        }
        #pragma unroll
        for (int n2 = 0; n2 < 4; n2++) {
            const int en = n2 * 8;
            bf[n2][0] = vw[(size_t)(en + gp) * PW + w0];
            bf[n2][1] = vw[(size_t)(en + gp) * PW + w1];
        }
        #pragma unroll
        for (int m2 = 0; m2 < 2; m2++)
            #pragma unroll
            for (int n2 = 0; n2 < 4; n2++)
                mma_f16(acc[m2][n2], af[m2], bf[n2]);
    }

    // scatter partials: c0,c1 -> row dm+gp cols 2tq,2tq+1; c2,c3 -> row +8
    #pragma unroll
    for (int m2 = 0; m2 < 2; m2++) {
        const int d = m2 * 16 + gp;
        #pragma unroll
        for (int n2 = 0; n2 < 4; n2++) {
            const int e = n2 * 8 + tq * 2;
            red[w][d    ][e    ] = acc[m2][n2][0];
            red[w][d    ][e + 1] = acc[m2][n2][1];
            red[w][d + 8][e    ] = acc[m2][n2][2];
            red[w][d + 8][e + 1] = acc[m2][n2][3];
        }
    }
    __syncthreads();

    #pragma unroll
    for (int c = tid * 4; c < tid * 4 + 4; c++) {
        float s = 0.f;
        #pragma unroll
        for (int ww = 0; ww < 8; ww++) s += red[ww][c >> 5][c & 31];
        atomicAdd(&g_ctx[bh * 1024 + c], s);
    }
}

// ---------------------------------------------------------------------------
// K2c v3: out = (ctx/ksum)^T * expq / colsum(expq) * scale.
// expq pre-computed fp16-packed; column sums via staged partials.
// Output: packed fp16 k-pairs along hid for the out-proj B.
// ---------------------------------------------------------------------------
__global__ __launch_bounds__(256)
void k_qout()
{
    __shared__ float qs[32][257];
    __shared__ float ctx[32][33];
    __shared__ float inv[32];
    __shared__ float cs[2][256];
    __shared__ float cinv[256];

    const int nt = blockIdx.x, h = blockIdx.y, b = blockIdx.z;
    const int tid = threadIdx.x;
    const int bh = b * HEADS + h;

    if (tid < 32) inv[tid] = 1.f / g_ksum[bh * 32 + tid];
    __syncthreads();
    #pragma unroll
    for (int i = tid; i < 1024; i += 256)
        ctx[i >> 5][i & 31] = g_ctx[bh * 1024 + i] * inv[i >> 5];

    // stage expq: thread (g2 = tid>>7, wd = tid&127) handles 16 rows stride 2
    const uint32_t* qw = g_qkvh + ((size_t)b * O3 + h * DH) * PW + nt * 128;
    const int wd = tid & 127, g2 = tid >> 7;
    float s0 = 0.f, s1 = 0.f;
    #pragma unroll
    for (int i = 0; i < 16; i++) {
        const int d = g2 + i * 2;
        float2 f = __half22float2(*(const __half2*)&qw[(size_t)d * PW + wd]);
        qs[d][2 * wd    ] = f.x;
        qs[d][2 * wd + 1] = f.y;
        s0 += f.x; s1 += f.y;
    }
    cs[g2][2 * wd    ] = s0;
    cs[g2][2 * wd + 1] = s1;
    __syncthreads();
    cinv[tid] = 0.17677669529663687f / (cs[0][tid] + cs[1][tid]);  // scale/colsum
    __syncthreads();

    const int w = tid >> 5, lane = tid & 31;
    float acc[4][8];
    #pragma unroll
    for (int i = 0; i < 4; i++)
        #pragma unroll
        for (int j = 0; j < 8; j++) acc[i][j] = 0.f;

    #pragma unroll
    for (int d = 0; d < 32; d++) {
        float ca[4], qa[8];
        #pragma unroll
        for (int i = 0; i < 4; i++) ca[i] = ctx[d][w * 4 + i];
        #pragma unroll
        for (int j = 0; j < 8; j++) qa[j] = qs[d][lane + 32 * j];
        #pragma unroll
        for (int i = 0; i < 4; i++)
            #pragma unroll
            for (int j = 0; j < 8; j++)
                acc[i][j] += ca[i] * qa[j];
    }

    uint32_t* obase = g_attn + ((size_t)b * (HID/2)) * NPIX + nt * 256;
    const int kw0 = h * 16 + w * 2;
    #pragma unroll
    for (int j = 0; j < 8; j++) {
        const int n = lane + 32 * j;
        const float civ = cinv[n];
        obase[(size_t)kw0       * NPIX + n] = pack2(acc[0][j] * civ, acc[1][j] * civ);
        obase[(size_t)(kw0 + 1) * NPIX + n] = pack2(acc[2][j] * civ, acc[3][j] * civ);
    }
}

// ---------------------------------------------------------------------------
// K4: in-place GroupNorm (per-batch stats) + per-channel affine
// ---------------------------------------------------------------------------
__global__ __launch_bounds__(256)
void k_gn(float* __restrict__ out,
          const float* __restrict__ gn_w,
          const float* __restrict__ gn_b)
{
    const size_t gid  = (size_t)blockIdx.x * blockDim.x + threadIdx.x;
    const size_t base = gid * 4;
    const int b = (int)(base >> 20);
    const int c = (int)((base >> 12) & 255);

    const float invN = 1.f / (256.f * 4096.f);
    const float mean = g_stats[2 * b + 0] * invN;
    const float var  = g_stats[2 * b + 1] * invN - mean * mean;
    const float r    = rsqrtf(var + EPS);
    const float w    = gn_w[c] * r;
    const float bb   = gn_b[c] - mean * w;

    float4 v = *(float4*)&out[base];
    v.x = v.x * w + bb;
    v.y = v.y * w + bb;
    v.z = v.z * w + bb;
    v.w = v.w * w + bb;
    *(float4*)&out[base] = v;
}

// ---------------------------------------------------------------------------
// Launch
// ---------------------------------------------------------------------------
extern "C" void kernel_launch(void* const* d_in, const int* in_sizes, int n_in,
                              void* d_out, int out_size)
{
    const float* x     = (const float*)d_in[0];
    const float* w_qkv = (const float*)d_in[1];
    const float* w_out = (const float*)d_in[2];
    const float* b_out = (const float*)d_in[3];
    const float* gn_w  = (const float*)d_in[4];
    const float* gn_b  = (const float*)d_in[5];
    float* out = (float*)d_out;

    uint32_t *p_qkvh, *p_attn;
    cudaGetSymbolAddress((void**)&p_qkvh, g_qkvh);
    cudaGetSymbolAddress((void**)&p_attn, g_attn);

    // K0: zero ctx + ksum + stats
    k_zero<<<(ZERO_N + 255) / 256, 256>>>();

    // K1: QKV projection (fp16 HMMA) -> exp(q),exp(k),v packed fp16 + ksum
    k_mma<CIN, O3, 0, false>
        <<<dim3(O3 / 128, NPIX / 128, BATCH), 256>>>(w_qkv, x, p_qkvh, nullptr);

    // K2: attention core
    k_ctx <<<dim3(NPIX / 1024, HEADS, BATCH), 256>>>();
    k_qout<<<dim3(NPIX / 256,  HEADS, BATCH), 256>>>();

    // K3: output projection + bias + stats  (B = packed fp16 attn)
    k_mma<HID, CIN, 1, true>
        <<<dim3(CIN / 128, NPIX / 128, BATCH), 256>>>(w_out, p_attn, out, b_out);

    // K4: GroupNorm normalize in place
    k_gn<<<(BATCH * CIN * NPIX / 4) / 256, 256>>>(out, gn_w, gn_b);
}

// round 13
// speedup vs baseline: 2.7824x; 1.0514x over previous
#include <cuda_runtime.h>
#include <cuda_fp16.h>
#include <cstdint>

// Problem constants
#define BATCH   32
#define CIN     256
#define NPIX    4096          // 64*64
#define HEADS   4
#define DH      32
#define HID     128           // HEADS*DH
#define O3      384           // 3*HID
#define EPS     1e-5f
#define PW      (NPIX / 2)    // fp16-pair words per row (2048)

// ---------------------------------------------------------------------------
// Scratch (device globals: allocation-free)
// ---------------------------------------------------------------------------
__device__ uint32_t g_qkvh[(size_t)BATCH * O3 * PW];          // 100 MB exp(q),exp(k),v
__device__ uint32_t g_attn[(size_t)BATCH * (HID/2) * NPIX];   //  34 MB packed along hid
__device__ uint32_t g_outh[(size_t)BATCH * CIN * PW];         //  67 MB out-proj fp16
__device__ float    g_stats[BATCH * 2];
__device__ float    g_ksum [BATCH * HEADS * 32];
__device__ float    g_ctx  [BATCH * HEADS * 32 * 32];

#define N_CTX  (BATCH * HEADS * 32 * 32)
#define N_KSUM (BATCH * HEADS * 32)
#define ZERO_N (N_CTX + N_KSUM + BATCH * 2)
__global__ void k_zero() {
    const int i = blockIdx.x * blockDim.x + threadIdx.x;
    if (i < N_CTX) g_ctx[i] = 0.f;
    else if (i < N_CTX + N_KSUM) g_ksum[i - N_CTX] = 0.f;
    else if (i < ZERO_N) g_stats[i - N_CTX - N_KSUM] = 0.f;
}

// ---------------------------------------------------------------------------
// helpers (sm_75/80-baseline PTX)
// ---------------------------------------------------------------------------
__device__ __forceinline__ uint32_t pack2(float lo, float hi) {
    __half2 h = __floats2half2_rn(lo, hi);
    return *reinterpret_cast<uint32_t*>(&h);
}
__device__ __forceinline__ void mma_f16(float c[4],
                                        const uint32_t a[4],
                                        const uint32_t b[2]) {
    asm volatile(
        "mma.sync.aligned.m16n8k16.row.col.f32.f16.f16.f32 "
        "{%0,%1,%2,%3}, {%4,%5,%6,%7}, {%8,%9}, {%0,%1,%2,%3};"
        : "+f"(c[0]), "+f"(c[1]), "+f"(c[2]), "+f"(c[3])
        : "r"(a[0]), "r"(a[1]), "r"(a[2]), "r"(a[3]),
          "r"(b[0]), "r"(b[1]));
}
__device__ __forceinline__ void ldmx4(uint32_t a[4], uint32_t addr) {
    asm volatile(
        "ldmatrix.sync.aligned.m8n8.x4.shared.b16 {%0,%1,%2,%3}, [%4];"
        : "=r"(a[0]), "=r"(a[1]), "=r"(a[2]), "=r"(a[3]) : "r"(addr));
}

// ---------------------------------------------------------------------------
// fp16 tensor-core GEMM:  C[z][M][4096] = A[M,K] * B[z][K,4096]
// CTA tile 128x128, BK=16, 8 warps (2m x 4n), warp tile 64x32.
// A fragments via ldmatrix.x4 (conflict-free with the m&4 chunk swizzle).
// MODE 0 (QKV): packed fp16 out (exp on q,k tiles, mt<2) + k-row exp-sums.
// MODE 1 (OUT): packed fp16 out + bias + fp32 per-batch sum/sumsq stats.
// BPK: B pre-packed fp16 (true) or fp32 (false).
// ---------------------------------------------------------------------------
template<int K, int M, int MODE, bool BPK>
__global__ __launch_bounds__(256)
void k_mma(const float* __restrict__ A, const void* __restrict__ Bg_,
           void* __restrict__ Cg, const float* __restrict__ bias)
{
    __shared__ uint32_t As[2][128][8];
    __shared__ uint32_t Bs[2][8][128];

    const int tid  = threadIdx.x, lane = tid & 31, wid = tid >> 5;
    const int wm   = wid >> 2, wn = wid & 3;
    const int tq   = lane & 3, gp = lane >> 2;
    const int mt   = blockIdx.x, nt = blockIdx.y, z = blockIdx.z;

    const float* Ap = A + (size_t)mt * 128 * K;
    const float*    Bpf = BPK ? nullptr
                     : (const float*)Bg_ + (size_t)z * K * NPIX + nt * 128;
    const uint32_t* Bpp = BPK
                     ? (const uint32_t*)Bg_ + (size_t)z * (K/2) * NPIX + nt * 128
                     : nullptr;

    const int am  = tid & 127, akw = (tid >> 7) * 4;
    const int bkw = tid >> 5;
    const int bn0 = lane * 4;

    // ldmatrix lane addressing (byte offset within one As stage):
    // row_in = (lane&8) + (lane&7); word base = ((lane&16)?4:0) ^ ((lane&7)&4)
    const int lr = lane & 7;
    const int row_in = ((lane & 8) ? 8 : 0) + lr;
    const int wb = (((lane & 16) ? 4 : 0)) ^ (lr & 4);
    const uint32_t asA =
        (uint32_t)__cvta_generic_to_shared(&As[0][0][0]);
    const uint32_t a_lane_off =
        (uint32_t)(((wm * 64 + row_in) * 8 + wb) * 4);

    float acc[4][4][4];
    #pragma unroll
    for (int i = 0; i < 4; i++)
        #pragma unroll
        for (int j = 0; j < 4; j++)
            #pragma unroll
            for (int r = 0; r < 4; r++) acc[i][j][r] = 0.f;

    float4 ra[2];
    float4 rbf[2];
    uint4  rbp;

    auto ldgA = [&](int t) {
        #pragma unroll
        for (int j = 0; j < 2; j++)
            ra[j] = *(const float4*)(Ap + (size_t)am * K + t * 16 + akw * 2 + j * 4);
    };
    auto stsA = [&](int t) {
        const int buf = t & 1;
        uint32_t w0 = pack2(ra[0].x, ra[0].y);
        uint32_t w1 = pack2(ra[0].z, ra[0].w);
        uint32_t w2 = pack2(ra[1].x, ra[1].y);
        uint32_t w3 = pack2(ra[1].z, ra[1].w);
        *(uint4*)&As[buf][am][akw ^ (am & 4)] = make_uint4(w0, w1, w2, w3);
    };
    auto ldgB = [&](int t) {
        if (BPK) {
            rbp = *(const uint4*)(Bpp + (size_t)(t * 8 + bkw) * NPIX + bn0);
        } else {
            rbf[0] = *(const float4*)(Bpf + (size_t)(t * 16 + 2 * bkw    ) * NPIX + bn0);
            rbf[1] = *(const float4*)(Bpf + (size_t)(t * 16 + 2 * bkw + 1) * NPIX + bn0);
        }
    };
    auto stsB = [&](int t) {
        const int buf = t & 1;
        const int col = bn0 ^ ((bkw & 3) * 8);
        if (BPK) {
            *(uint4*)&Bs[buf][bkw][col] = rbp;
        } else {
            *(uint4*)&Bs[buf][bkw][col] = make_uint4(
                pack2(rbf[0].x, rbf[1].x), pack2(rbf[0].y, rbf[1].y),
                pack2(rbf[0].z, rbf[1].z), pack2(rbf[0].w, rbf[1].w));
        }
    };
    auto compute = [&](int t) {
        const int buf = t & 1;
        const uint32_t abase = asA + (uint32_t)(buf * 128 * 8 * 4) + a_lane_off;
        uint32_t bf[4][2];
        #pragma unroll
        for (int nf = 0; nf < 4; nf++) {
            const int col = (wn * 32 + nf * 8 + gp) ^ (tq * 8);
            bf[nf][0] = Bs[buf][tq    ][col];
            bf[nf][1] = Bs[buf][tq + 4][col];
        }
        #pragma unroll
        for (int mf = 0; mf < 4; mf++) {
            uint32_t af[4];
            ldmx4(af, abase + (uint32_t)(mf * 16 * 8 * 4));
            #pragma unroll
            for (int nf = 0; nf < 4; nf++)
                mma_f16(acc[mf][nf], af, bf[nf]);
        }
    };

    constexpr int T = K / 16;

    ldgA(0); ldgB(0);
    stsA(0); stsB(0);
    ldgA(1); ldgB(1);
    __syncthreads();

    #pragma unroll 1
    for (int t = 0; t < T; t++) {
        compute(t);
        if (t + 1 < T) { stsA(t + 1); stsB(t + 1); }
        if (t + 2 < T) { ldgA(t + 2); ldgB(t + 2); }
        __syncthreads();
    }

    const int mg0 = mt * 128 + wm * 64;
    const int ng0 = nt * 128 + wn * 32;
    uint32_t* Cw = (uint32_t*)Cg + (size_t)z * M * PW;

    if (MODE == 0) {
        // --- QKV epilogue: exp on q,k + pack fp16 + ksum ---
        #pragma unroll
        for (int mf = 0; mf < 4; mf++) {
            const int r0 = mg0 + mf * 16 + gp;
            float s0 = 0.f, s1 = 0.f;
            #pragma unroll
            for (int nf = 0; nf < 4; nf++) {
                const int wc = (ng0 >> 1) + nf * 4 + tq;
                float a0 = acc[mf][nf][0], a1 = acc[mf][nf][1];
                float a2 = acc[mf][nf][2], a3 = acc[mf][nf][3];
                if (mt < 2) {
                    a0 = __expf(a0); a1 = __expf(a1);
                    a2 = __expf(a2); a3 = __expf(a3);
                }
                s0 += a0 + a1; s1 += a2 + a3;
                Cw[(size_t)r0      * PW + wc] = pack2(a0, a1);
                Cw[(size_t)(r0+8)  * PW + wc] = pack2(a2, a3);
            }
            if (mt == 1) {
                s0 += __shfl_xor_sync(0xffffffffu, s0, 1);
                s0 += __shfl_xor_sync(0xffffffffu, s0, 2);
                s1 += __shfl_xor_sync(0xffffffffu, s1, 1);
                s1 += __shfl_xor_sync(0xffffffffu, s1, 2);
                if (tq == 0) {
                    const int rk  = wm * 64 + mf * 16 + gp;
                    const int rk8 = rk + 8;
                    atomicAdd(&g_ksum[(z * HEADS + (rk  >> 5)) * 32 + (rk  & 31)], s0);
                    atomicAdd(&g_ksum[(z * HEADS + (rk8 >> 5)) * 32 + (rk8 & 31)], s1);
                }
            }
        }
    } else {
        // --- OUT epilogue: bias + stats (fp32 accs), packed fp16 store ---
        float lsum = 0.f, lsq = 0.f;
        #pragma unroll
        for (int mf = 0; mf < 4; mf++) {
            const int r0 = mg0 + mf * 16 + gp;
            const float bv0 = bias[r0];
            const float bv1 = bias[r0 + 8];
            #pragma unroll
            for (int nf = 0; nf < 4; nf++) {
                const int wc = (ng0 >> 1) + nf * 4 + tq;
                float a0 = acc[mf][nf][0] + bv0, a1 = acc[mf][nf][1] + bv0;
                float a2 = acc[mf][nf][2] + bv1, a3 = acc[mf][nf][3] + bv1;
                lsum += a0 + a1 + a2 + a3;
                lsq  += a0 * a0 + a1 * a1 + a2 * a2 + a3 * a3;
                Cw[(size_t)r0      * PW + wc] = pack2(a0, a1);
                Cw[(size_t)(r0+8)  * PW + wc] = pack2(a2, a3);
            }
        }
        __shared__ float rs[8], rq[8];
        #pragma unroll
        for (int o = 16; o; o >>= 1) {
            lsum += __shfl_xor_sync(0xffffffffu, lsum, o);
            lsq  += __shfl_xor_sync(0xffffffffu, lsq,  o);
        }
        if (lane == 0) { rs[wid] = lsum; rq[wid] = lsq; }
        __syncthreads();
        if (tid == 0) {
            float s = 0.f, q = 0.f;
            #pragma unroll
            for (int w = 0; w < 8; w++) { s += rs[w]; q += rq[w]; }
            atomicAdd(&g_stats[2 * z + 0], s);
            atomicAdd(&g_stats[2 * z + 1], q);
        }
    }
}

// ---------------------------------------------------------------------------
// K2b: ctx = expk @ v^T, pure fp16 MMA, gmem-direct fragments (unchanged)
// ---------------------------------------------------------------------------
__global__ __launch_bounds__(256)
void k_ctx()
{
    __shared__ float red[8][32][33];

    const int nt = blockIdx.x, h = blockIdx.y, b = blockIdx.z;
    const int tid = threadIdx.x, lane = tid & 31, w = tid >> 5;
    const int gp = lane >> 2, tq = lane & 3;
    const int bh = b * HEADS + h;

    const uint32_t* kw = g_qkvh + ((size_t)b * O3 + HID     + h * DH) * PW;
    const uint32_t* vw = g_qkvh + ((size_t)b * O3 + 2 * HID + h * DH) * PW;
    const int wb0 = nt * 512 + w * 64;

    float acc[2][4][4];
    #pragma unroll
    for (int i = 0; i < 2; i++)
        #pragma unroll
        for (int j = 0; j < 4; j++)
            #pragma unroll
            for (int r = 0; r < 4; r++) acc[i][j][r] = 0.f;

    #pragma unroll
    for (int kk = 0; kk < 8; kk++) {
        const int w0 = wb0 + kk * 8 + tq, w1 = w0 + 4;
        uint32_t af[2][4], bf[4][2];
        #pragma unroll
        for (int m2 = 0; m2 < 2; m2++) {
            const int dm = m2 * 16;
            af[m2][0] = kw[(size_t)(dm + gp    ) * PW + w0];
            af[m2][1] = kw[(size_t)(dm + gp + 8) * PW + w0];
            af[m2][2] = kw[(size_t)(dm + gp    ) * PW + w1];
            af[m2][3] = kw[(size_t)(dm + gp + 8) * PW + w1];
        }
        #pragma unroll
        for (int n2 = 0; n2 < 4; n2++) {
            const int en = n2 * 8;
            bf[n2][0] = vw[(size_t)(en + gp) * PW + w0];
            bf[n2][1] = vw[(size_t)(en + gp) * PW + w1];
        }
        #pragma unroll
        for (int m2 = 0; m2 < 2; m2++)
            #pragma unroll
            for (int n2 = 0; n2 < 4; n2++)
                mma_f16(acc[m2][n2], af[m2], bf[n2]);
    }

    #pragma unroll
    for (int m2 = 0; m2 < 2; m2++) {
        const int d = m2 * 16 + gp;
        #pragma unroll
        for (int n2 = 0; n2 < 4; n2++) {
            const int e = n2 * 8 + tq * 2;
            red[w][d    ][e    ] = acc[m2][n2][0];
            red[w][d    ][e + 1] = acc[m2][n2][1];
            red[w][d + 8][e    ] = acc[m2][n2][2];
            red[w][d + 8][e + 1] = acc[m2][n2][3];
        }
    }
    __syncthreads();

    #pragma unroll
    for (int c = tid * 4; c < tid * 4 + 4; c++) {
        float s = 0.f;
        #pragma unroll
        for (int ww = 0; ww < 8; ww++) s += red[ww][c >> 5][c & 31];
        atomicAdd(&g_ctx[bh * 1024 + c], s);
    }
}

// ---------------------------------------------------------------------------
// K2c: out = (ctx/ksum)^T * expq * scale/colsum; fp16-packed output (unchanged)
// ---------------------------------------------------------------------------
__global__ __launch_bounds__(256)
void k_qout()
{
    __shared__ float qs[32][257];
    __shared__ float ctx[32][33];
    __shared__ float inv[32];
    __shared__ float cs[2][256];
    __shared__ float cinv[256];

    const int nt = blockIdx.x, h = blockIdx.y, b = blockIdx.z;
    const int tid = threadIdx.x;
    const int bh = b * HEADS + h;

    if (tid < 32) inv[tid] = 1.f / g_ksum[bh * 32 + tid];
    __syncthreads();
    #pragma unroll
    for (int i = tid; i < 1024; i += 256)
        ctx[i >> 5][i & 31] = g_ctx[bh * 1024 + i] * inv[i >> 5];

    const uint32_t* qw = g_qkvh + ((size_t)b * O3 + h * DH) * PW + nt * 128;
    const int wd = tid & 127, g2 = tid >> 7;
    float s0 = 0.f, s1 = 0.f;
    #pragma unroll
    for (int i = 0; i < 16; i++) {
        const int d = g2 + i * 2;
        float2 f = __half22float2(*(const __half2*)&qw[(size_t)d * PW + wd]);
        qs[d][2 * wd    ] = f.x;
        qs[d][2 * wd + 1] = f.y;
        s0 += f.x; s1 += f.y;
    }
    cs[g2][2 * wd    ] = s0;
    cs[g2][2 * wd + 1] = s1;
    __syncthreads();
    cinv[tid] = 0.17677669529663687f / (cs[0][tid] + cs[1][tid]);
    __syncthreads();

    const int w = tid >> 5, lane = tid & 31;
    float acc[4][8];
    #pragma unroll
    for (int i = 0; i < 4; i++)
        #pragma unroll
        for (int j = 0; j < 8; j++) acc[i][j] = 0.f;

    #pragma unroll
    for (int d = 0; d < 32; d++) {
        float ca[4], qa[8];
        #pragma unroll
        for (int i = 0; i < 4; i++) ca[i] = ctx[d][w * 4 + i];
        #pragma unroll
        for (int j = 0; j < 8; j++) qa[j] = qs[d][lane + 32 * j];
        #pragma unroll
        for (int i = 0; i < 4; i++)
            #pragma unroll
            for (int j = 0; j < 8; j++)
                acc[i][j] += ca[i] * qa[j];
    }

    uint32_t* obase = g_attn + ((size_t)b * (HID/2)) * NPIX + nt * 256;
    const int kw0 = h * 16 + w * 2;
    #pragma unroll
    for (int j = 0; j < 8; j++) {
        const int n = lane + 32 * j;
        const float civ = cinv[n];
        obase[(size_t)kw0       * NPIX + n] = pack2(acc[0][j] * civ, acc[1][j] * civ);
        obase[(size_t)(kw0 + 1) * NPIX + n] = pack2(acc[2][j] * civ, acc[3][j] * civ);
    }
}

// ---------------------------------------------------------------------------
// K4: GroupNorm from packed fp16 out-proj result -> fp32 d_out
// ---------------------------------------------------------------------------
__global__ __launch_bounds__(256)
void k_gn(float* __restrict__ out,
          const float* __restrict__ gn_w,
          const float* __restrict__ gn_b)
{
    const size_t widx = ((size_t)blockIdx.x * blockDim.x + threadIdx.x) * 2;
    const int b = (int)(widx >> 19);             // 256*2048 words per batch
    const int c = (int)((widx >> 11) & 255);     // 2048 words per channel

    const float invN = 1.f / (256.f * 4096.f);
    const float mean = g_stats[2 * b + 0] * invN;
    const float var  = g_stats[2 * b + 1] * invN - mean * mean;
    const float r    = rsqrtf(var + EPS);
    const float w    = gn_w[c] * r;
    const float bb   = gn_b[c] - mean * w;

    const uint2 pw = *(const uint2*)&g_outh[widx];
    const float2 f0 = __half22float2(*(const __half2*)&pw.x);
    const float2 f1 = __half22float2(*(const __half2*)&pw.y);
    float4 v;
    v.x = f0.x * w + bb;
    v.y = f0.y * w + bb;
    v.z = f1.x * w + bb;
    v.w = f1.y * w + bb;
    *(float4*)&out[widx * 2] = v;
}

// ---------------------------------------------------------------------------
// Launch
// ---------------------------------------------------------------------------
extern "C" void kernel_launch(void* const* d_in, const int* in_sizes, int n_in,
                              void* d_out, int out_size)
{
    const float* x     = (const float*)d_in[0];
    const float* w_qkv = (const float*)d_in[1];
    const float* w_out = (const float*)d_in[2];
    const float* b_out = (const float*)d_in[3];
    const float* gn_w  = (const float*)d_in[4];
    const float* gn_b  = (const float*)d_in[5];
    float* out = (float*)d_out;

    uint32_t *p_qkvh, *p_attn, *p_outh;
    cudaGetSymbolAddress((void**)&p_qkvh, g_qkvh);
    cudaGetSymbolAddress((void**)&p_attn, g_attn);
    cudaGetSymbolAddress((void**)&p_outh, g_outh);

    // K0: zero ctx + ksum + stats
    k_zero<<<(ZERO_N + 255) / 256, 256>>>();

    // K1: QKV projection (fp16 HMMA + ldmatrix) -> exp(q),exp(k),v + ksum
    k_mma<CIN, O3, 0, false>
        <<<dim3(O3 / 128, NPIX / 128, BATCH), 256>>>(w_qkv, x, p_qkvh, nullptr);

    // K2: attention core
    k_ctx <<<dim3(NPIX / 1024, HEADS, BATCH), 256>>>();
    k_qout<<<dim3(NPIX / 256,  HEADS, BATCH), 256>>>();

    // K3: output projection + bias + stats -> packed fp16
    k_mma<HID, CIN, 1, true>
        <<<dim3(CIN / 128, NPIX / 128, BATCH), 256>>>(w_out, p_attn, p_outh, b_out);

    // K4: GroupNorm fp16 -> fp32 d_out
    k_gn<<<(BATCH * CIN * PW / 2) / 256, 256>>>(out, gn_w, gn_b);
}